// round 3
// baseline (speedup 1.0000x reference)
#include <cuda_runtime.h>
#include <math.h>

#define BB 2
#define SS 2048
#define DDIM 1024
#define HH 16
#define HDIM 64
#define FF 4096
#define MTOK (BB*SS)   /* 4096 rows */

// ---------------- scratch (static device arrays; no allocation) ----------------
__device__ float g_h  [MTOK*DDIM];   // LN output (reused for LN1 and LN2)
__device__ float g_q  [MTOK*DDIM];   // Q in (B,S,D) layout
__device__ float g_ctx[MTOK*DDIM];   // attention context in (B,S,D)
__device__ float g_x2 [MTOK*DDIM];   // post-attention residual
__device__ float g_ffn[MTOK*FF];     // gelu(h @ W1)

// ---------------- packed f32x2 helpers (sm_103a FFMA2 path) ----------------
__device__ __forceinline__ unsigned long long ffma2(unsigned long long a,
                                                    unsigned long long b,
                                                    unsigned long long c)
{
    unsigned long long d;
    asm("fma.rn.f32x2 %0, %1, %2, %3;" : "=l"(d) : "l"(a), "l"(b), "l"(c));
    return d;
}
__device__ __forceinline__ unsigned long long dup2(float x)
{
    unsigned long long d;
    unsigned int xi = __float_as_uint(x);
    asm("mov.b64 %0, {%1, %1};" : "=l"(d) : "r"(xi));
    return d;
}
__device__ __forceinline__ float lo2(unsigned long long v)
{
    return __uint_as_float((unsigned int)(v & 0xffffffffull));
}
__device__ __forceinline__ float hi2(unsigned long long v)
{
    return __uint_as_float((unsigned int)(v >> 32));
}

// ---------------- LayerNorm: one block per row, 256 threads ----------------
__global__ __launch_bounds__(256)
void ln_k(const float* __restrict__ x, const float* __restrict__ gg,
          const float* __restrict__ bb, float* __restrict__ out)
{
    __shared__ float red[32];
    int row = blockIdx.x;
    int tid = threadIdx.x;
    const float* xr = x + (size_t)row * DDIM;
    float4 v = *(const float4*)(xr + tid * 4);
    float s  = v.x + v.y + v.z + v.w;
    float s2 = v.x*v.x + v.y*v.y + v.z*v.z + v.w*v.w;
    #pragma unroll
    for (int off = 16; off; off >>= 1) {
        s  += __shfl_xor_sync(0xffffffffu, s,  off);
        s2 += __shfl_xor_sync(0xffffffffu, s2, off);
    }
    int warp = tid >> 5, lane = tid & 31;
    if (lane == 0) { red[warp] = s; red[warp + 8] = s2; }
    __syncthreads();
    if (tid == 0) {
        float ts = 0.f, ts2 = 0.f;
        #pragma unroll
        for (int w = 0; w < 8; ++w) { ts += red[w]; ts2 += red[w + 8]; }
        red[16] = ts; red[17] = ts2;
    }
    __syncthreads();
    float mean = red[16] * (1.0f / DDIM);
    float var  = red[17] * (1.0f / DDIM) - mean * mean;
    float inv  = rsqrtf(var + 1e-5f);
    float4 gv = *(const float4*)(gg + tid * 4);
    float4 bv = *(const float4*)(bb + tid * 4);
    float4 o;
    o.x = (v.x - mean) * inv * gv.x + bv.x;
    o.y = (v.y - mean) * inv * gv.y + bv.y;
    o.z = (v.z - mean) * inv * gv.z + bv.z;
    o.w = (v.w - mean) * inv * gv.w + bv.w;
    *(float4*)(out + (size_t)row * DDIM + tid * 4) = o;
}

// ---------------- SGEMM 128x128x16, 256 threads, 8x8 micro-tile, FFMA2 ----------------
#define GBM 128
#define GBN 128
#define GBK 16
#define ASTRIDE (GBM + 4)   /* 132: keeps float4 alignment, reduces store conflicts */

#define EPI_NONE 0
#define EPI_BHSD 1
#define EPI_GELU 2
#define EPI_RES  3

__device__ __forceinline__ float gelu_exact(float x) {
    return 0.5f * x * (1.0f + erff(x * 0.70710678118654752f));
}

template<int EPI>
__global__ __launch_bounds__(256, 2)
void sgemm_k(const float* __restrict__ A, const float* __restrict__ W,
             float* __restrict__ C, const float* __restrict__ R,
             int N, int K)
{
    __shared__ float As[GBK][ASTRIDE];
    __shared__ float Bs[GBK][GBN];
    int tid = threadIdx.x;
    int tx = tid & 15, ty = tid >> 4;
    int bm = blockIdx.y * GBM;
    int bn = blockIdx.x * GBN;

    const float* Ab = A + (size_t)bm * K;
    const float* Wb = W + bn;

    int ar[2], ak[2], bk[2], bc[2];
    float4 aR[2], bR[2];
    #pragma unroll
    for (int p = 0; p < 2; ++p) {
        int idx = tid + p * 256;
        ar[p] = idx >> 2;        ak[p] = (idx & 3) * 4;
        bk[p] = idx >> 5;        bc[p] = (idx & 31) * 4;
        aR[p] = *(const float4*)(Ab + (size_t)ar[p] * K + ak[p]);
        bR[p] = *(const float4*)(Wb + (size_t)bk[p] * N + bc[p]);
    }

    // packed accumulators: acc2[i][j] holds columns (2j, 2j+1) of row i
    unsigned long long acc2[8][4];
    #pragma unroll
    for (int i = 0; i < 8; ++i)
        #pragma unroll
        for (int j = 0; j < 4; ++j) acc2[i][j] = 0ull;

    #pragma unroll
    for (int p = 0; p < 2; ++p) {
        As[ak[p] + 0][ar[p]] = aR[p].x;
        As[ak[p] + 1][ar[p]] = aR[p].y;
        As[ak[p] + 2][ar[p]] = aR[p].z;
        As[ak[p] + 3][ar[p]] = aR[p].w;
        *(float4*)&Bs[bk[p]][bc[p]] = bR[p];
    }
    __syncthreads();

    int T = K / GBK;
    for (int t = 0; t < T; ++t) {
        if (t + 1 < T) {
            int k0 = (t + 1) * GBK;
            #pragma unroll
            for (int p = 0; p < 2; ++p) {
                aR[p] = *(const float4*)(Ab + (size_t)ar[p] * K + k0 + ak[p]);
                bR[p] = *(const float4*)(Wb + (size_t)(k0 + bk[p]) * N + bc[p]);
            }
        }
        #pragma unroll
        for (int kk = 0; kk < GBK; ++kk) {
            float af[8];
            *(float4*)&af[0] = *(const float4*)&As[kk][ty * 8];
            *(float4*)&af[4] = *(const float4*)&As[kk][ty * 8 + 4];
            unsigned long long b2[4];
            const unsigned long long* bp =
                (const unsigned long long*)&Bs[kk][tx * 8];
            b2[0] = bp[0]; b2[1] = bp[1]; b2[2] = bp[2]; b2[3] = bp[3];
            #pragma unroll
            for (int i = 0; i < 8; ++i) {
                unsigned long long a2 = dup2(af[i]);
                #pragma unroll
                for (int j = 0; j < 4; ++j)
                    acc2[i][j] = ffma2(a2, b2[j], acc2[i][j]);
            }
        }
        __syncthreads();
        if (t + 1 < T) {
            #pragma unroll
            for (int p = 0; p < 2; ++p) {
                As[ak[p] + 0][ar[p]] = aR[p].x;
                As[ak[p] + 1][ar[p]] = aR[p].y;
                As[ak[p] + 2][ar[p]] = aR[p].z;
                As[ak[p] + 3][ar[p]] = aR[p].w;
                *(float4*)&Bs[bk[p]][bc[p]] = bR[p];
            }
            __syncthreads();
        }
    }

    // epilogue
    int r0 = bm + ty * 8;
    int c0 = bn + tx * 8;
    #pragma unroll
    for (int i = 0; i < 8; ++i) {
        int r = r0 + i;
        #pragma unroll
        for (int jj = 0; jj < 2; ++jj) {
            int c = c0 + jj * 4;
            float4 o;
            o.x = lo2(acc2[i][jj * 2 + 0]);
            o.y = hi2(acc2[i][jj * 2 + 0]);
            o.z = lo2(acc2[i][jj * 2 + 1]);
            o.w = hi2(acc2[i][jj * 2 + 1]);
            if (EPI == EPI_GELU) {
                o.x = gelu_exact(o.x); o.y = gelu_exact(o.y);
                o.z = gelu_exact(o.z); o.w = gelu_exact(o.w);
            }
            if (EPI == EPI_BHSD) {
                int b = r >> 11, s = r & 2047;
                int h = c >> 6,  hd = c & 63;
                size_t off = (((size_t)(b * HH + h)) * SS + s) * HDIM + hd;
                *(float4*)(C + off) = o;
            } else if (EPI == EPI_RES) {
                size_t off = (size_t)r * N + c;
                float4 rv = *(const float4*)(R + off);
                o.x += rv.x; o.y += rv.y; o.z += rv.z; o.w += rv.w;
                *(float4*)(C + off) = o;
            } else {
                *(float4*)(C + (size_t)r * N + c) = o;
            }
        }
    }
}

// ---------------- Flash attention (fp32, causal, 64q x 64k tiles) ----------------
#define FSTR 65
#define FLASH_SMEM (4 * 64 * FSTR * 4)   /* 66560 bytes */

__global__ __launch_bounds__(128)
void flash_k(const float* __restrict__ q, const float* __restrict__ kg,
             const float* __restrict__ vg, float* __restrict__ ctx)
{
    extern __shared__ float sm[];
    float* Qs = sm;
    float* Ks = Qs + 64 * FSTR;
    float* Vs = Ks + 64 * FSTR;
    float* Ps = Vs + 64 * FSTR;

    int qt = blockIdx.x;      // query tile 0..31
    int bh = blockIdx.y;      // 0..31
    int b = bh >> 4, h = bh & 15;
    int tid = threadIdx.x;
    int tx = tid & 15, ty = tid >> 4;   // ty in [0,8)

    const float* qb = q  + ((size_t)(b * SS + qt * 64)) * DDIM + h * HDIM;
    const float* kb = kg + (size_t)bh * SS * HDIM;
    const float* vb = vg + (size_t)bh * SS * HDIM;

    // load & pre-scale Q tile (64 x 64)
    for (int i = tid; i < 1024; i += 128) {
        int r = i >> 4, c = (i & 15) * 4;
        float4 v4 = *(const float4*)(qb + (size_t)r * DDIM + c);
        Qs[r * FSTR + c + 0] = v4.x * 0.125f;
        Qs[r * FSTR + c + 1] = v4.y * 0.125f;
        Qs[r * FSTR + c + 2] = v4.z * 0.125f;
        Qs[r * FSTR + c + 3] = v4.w * 0.125f;
    }

    float m[8], l[8], o[8][4];
    #pragma unroll
    for (int i = 0; i < 8; ++i) {
        m[i] = -1e30f; l[i] = 0.f;
        #pragma unroll
        for (int j = 0; j < 4; ++j) o[i][j] = 0.f;
    }
    __syncthreads();

    for (int kt = 0; kt <= qt; ++kt) {
        const float* kp = kb + (size_t)kt * 4096;
        const float* vp = vb + (size_t)kt * 4096;
        for (int i = tid; i < 1024; i += 128) {
            int r = i >> 4, c = (i & 15) * 4;
            float4 kv = *(const float4*)(kp + i * 4);
            Ks[r * FSTR + c + 0] = kv.x; Ks[r * FSTR + c + 1] = kv.y;
            Ks[r * FSTR + c + 2] = kv.z; Ks[r * FSTR + c + 3] = kv.w;
            float4 vv = *(const float4*)(vp + i * 4);
            Vs[r * FSTR + c + 0] = vv.x; Vs[r * FSTR + c + 1] = vv.y;
            Vs[r * FSTR + c + 2] = vv.z; Vs[r * FSTR + c + 3] = vv.w;
        }
        __syncthreads();

        float s[8][4];
        #pragma unroll
        for (int i = 0; i < 8; ++i)
            #pragma unroll
            for (int j = 0; j < 4; ++j) s[i][j] = 0.f;

        #pragma unroll 4
        for (int d = 0; d < 64; ++d) {
            float bb4[4], aa[8];
            #pragma unroll
            for (int j = 0; j < 4; ++j) bb4[j] = Ks[(tx * 4 + j) * FSTR + d];
            #pragma unroll
            for (int i = 0; i < 8; ++i) aa[i] = Qs[(ty * 8 + i) * FSTR + d];
            #pragma unroll
            for (int i = 0; i < 8; ++i)
                #pragma unroll
                for (int j = 0; j < 4; ++j)
                    s[i][j] = fmaf(aa[i], bb4[j], s[i][j]);
        }

        if (kt == qt) {
            #pragma unroll
            for (int i = 0; i < 8; ++i)
                #pragma unroll
                for (int j = 0; j < 4; ++j)
                    if (tx * 4 + j > ty * 8 + i) s[i][j] = -1e30f;
        }

        #pragma unroll
        for (int i = 0; i < 8; ++i) {
            float rm = fmaxf(fmaxf(s[i][0], s[i][1]), fmaxf(s[i][2], s[i][3]));
            rm = fmaxf(rm, __shfl_xor_sync(0xffffffffu, rm, 8));
            rm = fmaxf(rm, __shfl_xor_sync(0xffffffffu, rm, 4));
            rm = fmaxf(rm, __shfl_xor_sync(0xffffffffu, rm, 2));
            rm = fmaxf(rm, __shfl_xor_sync(0xffffffffu, rm, 1));
            float mnew = fmaxf(m[i], rm);
            float sc = __expf(m[i] - mnew);
            float rs = 0.f;
            #pragma unroll
            for (int j = 0; j < 4; ++j) {
                float p = __expf(s[i][j] - mnew);
                s[i][j] = p; rs += p;
                Ps[(ty * 8 + i) * FSTR + tx * 4 + j] = p;
            }
            rs += __shfl_xor_sync(0xffffffffu, rs, 8);
            rs += __shfl_xor_sync(0xffffffffu, rs, 4);
            rs += __shfl_xor_sync(0xffffffffu, rs, 2);
            rs += __shfl_xor_sync(0xffffffffu, rs, 1);
            l[i] = l[i] * sc + rs;
            m[i] = mnew;
            #pragma unroll
            for (int j = 0; j < 4; ++j) o[i][j] *= sc;
        }
        __syncthreads();

        #pragma unroll 4
        for (int kk = 0; kk < 64; ++kk) {
            float vv4[4], pv[8];
            #pragma unroll
            for (int j = 0; j < 4; ++j) vv4[j] = Vs[kk * FSTR + tx * 4 + j];
            #pragma unroll
            for (int i = 0; i < 8; ++i) pv[i] = Ps[(ty * 8 + i) * FSTR + kk];
            #pragma unroll
            for (int i = 0; i < 8; ++i)
                #pragma unroll
                for (int j = 0; j < 4; ++j)
                    o[i][j] = fmaf(pv[i], vv4[j], o[i][j]);
        }
        __syncthreads();
    }

    #pragma unroll
    for (int i = 0; i < 8; ++i) {
        int r = qt * 64 + ty * 8 + i;
        float invl = 1.0f / l[i];
        float4 ov;
        ov.x = o[i][0] * invl; ov.y = o[i][1] * invl;
        ov.z = o[i][2] * invl; ov.w = o[i][3] * invl;
        *(float4*)(ctx + ((size_t)(b * SS + r)) * DDIM + h * HDIM + tx * 4) = ov;
    }
}

// ---------------- launch ----------------
extern "C" void kernel_launch(void* const* d_in, const int* in_sizes, int n_in,
                              void* d_out, int out_size)
{
    const float* x    = (const float*)d_in[0];
    /* d_in[1] = attention_mask (pure causal; reproduced in-kernel) */
    const float* ln1g = (const float*)d_in[2];
    const float* ln1b = (const float*)d_in[3];
    const float* Wq   = (const float*)d_in[4];
    const float* Wk   = (const float*)d_in[5];
    const float* Wv   = (const float*)d_in[6];
    const float* Wo   = (const float*)d_in[7];
    const float* ln2g = (const float*)d_in[8];
    const float* ln2b = (const float*)d_in[9];
    const float* W1   = (const float*)d_in[10];
    const float* W2   = (const float*)d_in[11];

    float* out  = (float*)d_out;
    float* kout = out  + (size_t)MTOK * DDIM;
    float* vout = kout + (size_t)MTOK * DDIM;

    float *h, *qs, *ctx, *x2, *ffn;
    cudaGetSymbolAddress((void**)&h,   g_h);
    cudaGetSymbolAddress((void**)&qs,  g_q);
    cudaGetSymbolAddress((void**)&ctx, g_ctx);
    cudaGetSymbolAddress((void**)&x2,  g_x2);
    cudaGetSymbolAddress((void**)&ffn, g_ffn);

    cudaFuncSetAttribute(flash_k, cudaFuncAttributeMaxDynamicSharedMemorySize,
                         FLASH_SMEM);

    dim3 gQKV(DDIM / GBN, MTOK / GBM);   // (8, 32)
    dim3 gFFN(FF   / GBN, MTOK / GBM);   // (32, 32)

    // 1) LN1
    ln_k<<<MTOK, 256>>>(x, ln1g, ln1b, h);
    // 2-4) Q,K,V projections (K,V straight into d_out in (B,H,S,HD) layout)
    sgemm_k<EPI_NONE><<<gQKV, 256>>>(h, Wq, qs,   nullptr, DDIM, DDIM);
    sgemm_k<EPI_BHSD><<<gQKV, 256>>>(h, Wk, kout, nullptr, DDIM, DDIM);
    sgemm_k<EPI_BHSD><<<gQKV, 256>>>(h, Wv, vout, nullptr, DDIM, DDIM);
    // 5) causal flash attention, writes ctx in (B,S,D)
    flash_k<<<dim3(SS / 64, BB * HH), 128, FLASH_SMEM>>>(qs, kout, vout, ctx);
    // 6) output projection + residual
    sgemm_k<EPI_RES><<<gQKV, 256>>>(ctx, Wo, x2, x, DDIM, DDIM);
    // 7) LN2
    ln_k<<<MTOK, 256>>>(x2, ln2g, ln2b, h);
    // 8) FFN up + exact gelu
    sgemm_k<EPI_GELU><<<gFFN, 256>>>(h, W1, ffn, nullptr, FF, DDIM);
    // 9) FFN down + residual -> out
    sgemm_k<EPI_RES><<<gQKV, 256>>>(ffn, W2, out, x2, DDIM, FF);
}

// round 5
// speedup vs baseline: 1.6944x; 1.6944x over previous
#include <cuda_runtime.h>
#include <cuda_bf16.h>
#include <math.h>
#include <stdint.h>

#define BB 2
#define SS 2048
#define DDIM 1024
#define HH 16
#define HDIM 64
#define FF 4096
#define MTOK (BB*SS)

// ---------------- scratch ----------------
__device__ __align__(128) float g_q  [MTOK*DDIM];
__device__ __align__(128) float g_x2 [MTOK*DDIM];
__device__ __align__(128) __nv_bfloat16 g_hh [MTOK*DDIM];
__device__ __align__(128) __nv_bfloat16 g_hl [MTOK*DDIM];
__device__ __align__(128) __nv_bfloat16 g_cxh[MTOK*DDIM];
__device__ __align__(128) __nv_bfloat16 g_cxl[MTOK*DDIM];
__device__ __align__(128) __nv_bfloat16 g_fh [MTOK*FF];
__device__ __align__(128) __nv_bfloat16 g_fl [MTOK*FF];
#define WT_TOTAL 12582912
__device__ __align__(128) __nv_bfloat16 g_wth[WT_TOTAL];
__device__ __align__(128) __nv_bfloat16 g_wtl[WT_TOTAL];

// ---------------- helpers ----------------
__device__ __forceinline__ uint32_t smem_u32(const void* p) {
    uint32_t a;
    asm("{ .reg .u64 t; cvta.to.shared.u64 t, %1; cvt.u32.u64 %0, t; }" : "=r"(a) : "l"(p));
    return a;
}
__device__ __forceinline__ void cp16(uint32_t dst, const void* src) {
    asm volatile("cp.async.cg.shared.global [%0], [%1], 16;" :: "r"(dst), "l"(src) : "memory");
}
#define CP_COMMIT() asm volatile("cp.async.commit_group;" ::: "memory")
#define CP_WAIT(n)  asm volatile("cp.async.wait_group %0;" :: "n"(n) : "memory")

__device__ __forceinline__ void ldsm4(uint32_t* r, uint32_t addr) {
    asm volatile("ldmatrix.sync.aligned.m8n8.x4.shared.b16 {%0,%1,%2,%3}, [%4];"
        : "=r"(r[0]), "=r"(r[1]), "=r"(r[2]), "=r"(r[3]) : "r"(addr));
}
__device__ __forceinline__ void mma16816(float* c, const uint32_t* a, const uint32_t* b) {
    asm volatile("mma.sync.aligned.m16n8k16.row.col.f32.bf16.bf16.f32 "
        "{%0,%1,%2,%3}, {%4,%5,%6,%7}, {%8,%9}, {%0,%1,%2,%3};"
        : "+f"(c[0]), "+f"(c[1]), "+f"(c[2]), "+f"(c[3])
        : "r"(a[0]), "r"(a[1]), "r"(a[2]), "r"(a[3]), "r"(b[0]), "r"(b[1]));
}
__device__ __forceinline__ void split_bf16(float x, __nv_bfloat16& h, __nv_bfloat16& l) {
    h = __float2bfloat16_rn(x);
    l = __float2bfloat16_rn(x - __bfloat162float(h));
}
__device__ __forceinline__ float gelu_exact(float x) {
    return 0.5f * x * (1.0f + erff(x * 0.70710678118654752f));
}

// ---------------- LayerNorm -> bf16 hi/lo ----------------
__global__ __launch_bounds__(256)
void ln_k(const float* __restrict__ x, const float* __restrict__ gg,
          const float* __restrict__ bb,
          __nv_bfloat16* __restrict__ oh, __nv_bfloat16* __restrict__ ol)
{
    __shared__ float red[32];
    int row = blockIdx.x, tid = threadIdx.x;
    float4 v = *(const float4*)(x + (size_t)row * DDIM + tid * 4);
    float s = v.x + v.y + v.z + v.w;
    float s2 = v.x*v.x + v.y*v.y + v.z*v.z + v.w*v.w;
    #pragma unroll
    for (int off = 16; off; off >>= 1) {
        s  += __shfl_xor_sync(0xffffffffu, s,  off);
        s2 += __shfl_xor_sync(0xffffffffu, s2, off);
    }
    int warp = tid >> 5, lane = tid & 31;
    if (lane == 0) { red[warp] = s; red[warp + 8] = s2; }
    __syncthreads();
    if (tid == 0) {
        float ts = 0.f, ts2 = 0.f;
        #pragma unroll
        for (int w = 0; w < 8; ++w) { ts += red[w]; ts2 += red[w + 8]; }
        red[16] = ts; red[17] = ts2;
    }
    __syncthreads();
    float mean = red[16] * (1.0f / DDIM);
    float var  = red[17] * (1.0f / DDIM) - mean * mean;
    float inv  = rsqrtf(var + 1e-5f);
    float4 gv = *(const float4*)(gg + tid * 4);
    float4 bv = *(const float4*)(bb + tid * 4);
    float o0 = (v.x-mean)*inv*gv.x + bv.x, o1 = (v.y-mean)*inv*gv.y + bv.y;
    float o2 = (v.z-mean)*inv*gv.z + bv.z, o3 = (v.w-mean)*inv*gv.w + bv.w;
    __nv_bfloat16 h0,h1,h2,h3,l0,l1,l2,l3;
    split_bf16(o0,h0,l0); split_bf16(o1,h1,l1); split_bf16(o2,h2,l2); split_bf16(o3,h3,l3);
    size_t off = (size_t)row * DDIM + tid * 4;
    ((__nv_bfloat162*)(oh+off))[0] = __halves2bfloat162(h0,h1);
    ((__nv_bfloat162*)(oh+off))[1] = __halves2bfloat162(h2,h3);
    ((__nv_bfloat162*)(ol+off))[0] = __halves2bfloat162(l0,l1);
    ((__nv_bfloat162*)(ol+off))[1] = __halves2bfloat162(l2,l3);
}

// ---------------- weight transpose + split: W[K,N] -> T[N,K] hi/lo ----------------
__global__ __launch_bounds__(256)
void wtrans_k(const float* __restrict__ W, __nv_bfloat16* __restrict__ Th,
              __nv_bfloat16* __restrict__ Tl, int K, int N)
{
    __shared__ __nv_bfloat16 sh[64][65], sl[64][65];
    int n0 = blockIdx.x * 64, k0 = blockIdx.y * 64, tid = threadIdx.x;
    for (int idx = tid; idx < 4096; idx += 256) {
        int i = idx >> 6, j = idx & 63;
        float w = W[(size_t)(k0 + i) * N + n0 + j];
        __nv_bfloat16 h, l; split_bf16(w, h, l);
        sh[i][j] = h; sl[i][j] = l;
    }
    __syncthreads();
    for (int idx = tid; idx < 4096; idx += 256) {
        int n = idx >> 6, k = idx & 63;
        size_t off = (size_t)(n0 + n) * K + k0 + k;
        Th[off] = sh[k][n]; Tl[off] = sl[k][n];
    }
}

// ---------------- mma.sync GEMM 128x128, bf16 hi/lo, fp32 accum ----------------
// A[M,K] bf16 hi/lo row-major; B[N,K] bf16 hi/lo row-major (K contiguous)
#define EPI_NONE 0
#define EPI_BHSD 1
#define EPI_GELU 2
#define EPI_RES  3
#define APITCH 80                 /* bytes per smem row: 32 bf16 + 8 pad */
#define STAGE_B 40960             /* 4 arrays * 128 * 80 */
#define GSMEM (2 * STAGE_B)

template<int EPI>
__global__ __launch_bounds__(256, 1)
void mma_gemm(const __nv_bfloat16* __restrict__ Ah, const __nv_bfloat16* __restrict__ Al,
              const __nv_bfloat16* __restrict__ Bh, const __nv_bfloat16* __restrict__ Bl,
              float* __restrict__ C, __nv_bfloat16* __restrict__ Ch,
              __nv_bfloat16* __restrict__ Cl, const float* __restrict__ R, int N, int K)
{
    extern __shared__ __align__(1024) char smem[];
    const uint32_t sbase = smem_u32(smem);
    const int tid = threadIdx.x, wid = tid >> 5, l = tid & 31;
    const int m0 = blockIdx.y * 128, n0 = blockIdx.x * 128;
    const int wm = wid >> 1, wn = wid & 1;     // warp tile: rows wm*32, cols wn*64

    // ldmatrix per-lane offsets (bytes)
    const uint32_t aoff = (uint32_t)(((l & 7) + ((l >> 3) & 1) * 8) * APITCH + (l >> 4) * 16);
    const uint32_t boff = (uint32_t)(((l & 7) + (l >> 4) * 8) * APITCH + ((l >> 3) & 1) * 16);

    float acc[2][8][4];
    #pragma unroll
    for (int i = 0; i < 2; ++i)
        #pragma unroll
        for (int j = 0; j < 8; ++j)
            #pragma unroll
            for (int q = 0; q < 4; ++q) acc[i][j][q] = 0.f;

    const int T = K >> 5;   // k32 stages

    auto ld_stage = [&](int s) {
        uint32_t dst = sbase + (uint32_t)((s & 1) * STAGE_B);
        int ko = s * 32;
        #pragma unroll
        for (int q = 0; q < 2; ++q) {
            int idx = tid + q * 256;
            int r = idx >> 2, c = idx & 3;           // r in [0,128), c in [0,4) 16B units
            uint32_t so = dst + (uint32_t)(r * APITCH + c * 16);
            size_t ga = (size_t)(m0 + r) * K + ko + c * 8;
            size_t gb = (size_t)(n0 + r) * K + ko + c * 8;
            cp16(so,             Ah + ga);
            cp16(so + 10240,     Al + ga);
            cp16(so + 20480,     Bh + gb);
            cp16(so + 30720,     Bl + gb);
        }
    };

    ld_stage(0); CP_COMMIT();
    for (int s = 0; s < T; ++s) {
        if (s + 1 < T) { ld_stage(s + 1); CP_COMMIT(); CP_WAIT(1); }
        else           { CP_WAIT(0); }
        __syncthreads();
        uint32_t buf = sbase + (uint32_t)((s & 1) * STAGE_B);
        uint32_t bufAh = buf,          bufAl = buf + 10240;
        uint32_t bufBh = buf + 20480,  bufBl = buf + 30720;
        #pragma unroll
        for (int kk = 0; kk < 2; ++kk) {
            uint32_t kb = (uint32_t)(kk * 32);
            uint32_t ah[2][4], al[2][4], bh[8][2], bl[8][2];
            #pragma unroll
            for (int i = 0; i < 2; ++i) {
                uint32_t ro = (uint32_t)((wm * 32 + i * 16) * APITCH);
                ldsm4(ah[i], bufAh + ro + aoff + kb);
                ldsm4(al[i], bufAl + ro + aoff + kb);
            }
            #pragma unroll
            for (int jp = 0; jp < 4; ++jp) {
                uint32_t ro = (uint32_t)((wn * 64 + jp * 16) * APITCH);
                uint32_t rh[4], rl[4];
                ldsm4(rh, bufBh + ro + boff + kb);
                ldsm4(rl, bufBl + ro + boff + kb);
                bh[jp*2+0][0] = rh[0]; bh[jp*2+0][1] = rh[1];
                bh[jp*2+1][0] = rh[2]; bh[jp*2+1][1] = rh[3];
                bl[jp*2+0][0] = rl[0]; bl[jp*2+0][1] = rl[1];
                bl[jp*2+1][0] = rl[2]; bl[jp*2+1][1] = rl[3];
            }
            #pragma unroll
            for (int i = 0; i < 2; ++i)
                #pragma unroll
                for (int j = 0; j < 8; ++j) {
                    mma16816(acc[i][j], ah[i], bh[j]);
                    mma16816(acc[i][j], ah[i], bl[j]);
                    mma16816(acc[i][j], al[i], bh[j]);
                }
        }
        __syncthreads();
    }

    // ---- epilogue: registers -> gmem ----
    #pragma unroll
    for (int i = 0; i < 2; ++i)
        #pragma unroll
        for (int j = 0; j < 8; ++j)
            #pragma unroll
            for (int h2 = 0; h2 < 2; ++h2) {
                int r = m0 + wm * 32 + i * 16 + (l >> 2) + h2 * 8;
                int col = n0 + wn * 64 + j * 8 + (l & 3) * 2;
                float v0 = acc[i][j][h2 * 2 + 0];
                float v1 = acc[i][j][h2 * 2 + 1];
                if (EPI == EPI_GELU) {
                    v0 = gelu_exact(v0); v1 = gelu_exact(v1);
                    __nv_bfloat16 h0, h1, l0, l1;
                    split_bf16(v0, h0, l0); split_bf16(v1, h1, l1);
                    size_t off = (size_t)r * N + col;
                    *(__nv_bfloat162*)(Ch + off) = __halves2bfloat162(h0, h1);
                    *(__nv_bfloat162*)(Cl + off) = __halves2bfloat162(l0, l1);
                } else if (EPI == EPI_BHSD) {
                    int bb = r >> 11, sx = r & 2047;
                    int hidx = col >> 6, hd = col & 63;
                    size_t off = (((size_t)(bb * HH + hidx)) * SS + sx) * HDIM + hd;
                    float2 o; o.x = v0; o.y = v1;
                    *(float2*)(C + off) = o;
                } else if (EPI == EPI_RES) {
                    size_t off = (size_t)r * N + col;
                    float2 rv = *(const float2*)(R + off);
                    float2 o; o.x = v0 + rv.x; o.y = v1 + rv.y;
                    *(float2*)(C + off) = o;
                } else {
                    size_t off = (size_t)r * N + col;
                    float2 o; o.x = v0; o.y = v1;
                    *(float2*)(C + off) = o;
                }
            }
}

// ---------------- Flash attention (fp32, causal) -> bf16 hi/lo ctx ----------------
#define FSTR 65
#define FLASH_SMEM (4 * 64 * FSTR * 4)

__global__ __launch_bounds__(128)
void flash_k(const float* __restrict__ q, const float* __restrict__ kg,
             const float* __restrict__ vg,
             __nv_bfloat16* __restrict__ cxh, __nv_bfloat16* __restrict__ cxl)
{
    extern __shared__ float sm[];
    float* Qs = sm;
    float* Ks = Qs + 64 * FSTR;
    float* Vs = Ks + 64 * FSTR;
    float* Ps = Vs + 64 * FSTR;

    int qt = blockIdx.x, bh = blockIdx.y;
    int b = bh >> 4, h = bh & 15;
    int tid = threadIdx.x, tx = tid & 15, ty = tid >> 4;

    const float* qb = q  + ((size_t)(b * SS + qt * 64)) * DDIM + h * HDIM;
    const float* kb = kg + (size_t)bh * SS * HDIM;
    const float* vb = vg + (size_t)bh * SS * HDIM;

    for (int i = tid; i < 1024; i += 128) {
        int r = i >> 4, c = (i & 15) * 4;
        float4 v4 = *(const float4*)(qb + (size_t)r * DDIM + c);
        Qs[r*FSTR+c+0] = v4.x*0.125f; Qs[r*FSTR+c+1] = v4.y*0.125f;
        Qs[r*FSTR+c+2] = v4.z*0.125f; Qs[r*FSTR+c+3] = v4.w*0.125f;
    }
    float m[8], l[8], o[8][4];
    #pragma unroll
    for (int i = 0; i < 8; ++i) {
        m[i] = -1e30f; l[i] = 0.f;
        #pragma unroll
        for (int j = 0; j < 4; ++j) o[i][j] = 0.f;
    }
    __syncthreads();

    for (int kt = 0; kt <= qt; ++kt) {
        const float* kp = kb + (size_t)kt * 4096;
        const float* vp = vb + (size_t)kt * 4096;
        for (int i = tid; i < 1024; i += 128) {
            int r = i >> 4, c = (i & 15) * 4;
            float4 kv = *(const float4*)(kp + i * 4);
            Ks[r*FSTR+c+0]=kv.x; Ks[r*FSTR+c+1]=kv.y; Ks[r*FSTR+c+2]=kv.z; Ks[r*FSTR+c+3]=kv.w;
            float4 vv = *(const float4*)(vp + i * 4);
            Vs[r*FSTR+c+0]=vv.x; Vs[r*FSTR+c+1]=vv.y; Vs[r*FSTR+c+2]=vv.z; Vs[r*FSTR+c+3]=vv.w;
        }
        __syncthreads();

        float s[8][4];
        #pragma unroll
        for (int i = 0; i < 8; ++i)
            #pragma unroll
            for (int j = 0; j < 4; ++j) s[i][j] = 0.f;

        #pragma unroll 4
        for (int d = 0; d < 64; ++d) {
            float bb4[4], aa[8];
            #pragma unroll
            for (int j = 0; j < 4; ++j) bb4[j] = Ks[(tx*4+j)*FSTR + d];
            #pragma unroll
            for (int i = 0; i < 8; ++i) aa[i] = Qs[(ty*8+i)*FSTR + d];
            #pragma unroll
            for (int i = 0; i < 8; ++i)
                #pragma unroll
                for (int j = 0; j < 4; ++j)
                    s[i][j] = fmaf(aa[i], bb4[j], s[i][j]);
        }
        if (kt == qt) {
            #pragma unroll
            for (int i = 0; i < 8; ++i)
                #pragma unroll
                for (int j = 0; j < 4; ++j)
                    if (tx*4+j > ty*8+i) s[i][j] = -1e30f;
        }
        #pragma unroll
        for (int i = 0; i < 8; ++i) {
            float rm = fmaxf(fmaxf(s[i][0], s[i][1]), fmaxf(s[i][2], s[i][3]));
            rm = fmaxf(rm, __shfl_xor_sync(0xffffffffu, rm, 8));
            rm = fmaxf(rm, __shfl_xor_sync(0xffffffffu, rm, 4));
            rm = fmaxf(rm, __shfl_xor_sync(0xffffffffu, rm, 2));
            rm = fmaxf(rm, __shfl_xor_sync(0xffffffffu, rm, 1));
            float mnew = fmaxf(m[i], rm);
            float sc = __expf(m[i] - mnew);
            float rs = 0.f;
            #pragma unroll
            for (int j = 0; j < 4; ++j) {
                float p = __expf(s[i][j] - mnew);
                s[i][j] = p; rs += p;
                Ps[(ty*8+i)*FSTR + tx*4+j] = p;
            }
            rs += __shfl_xor_sync(0xffffffffu, rs, 8);
            rs += __shfl_xor_sync(0xffffffffu, rs, 4);
            rs += __shfl_xor_sync(0xffffffffu, rs, 2);
            rs += __shfl_xor_sync(0xffffffffu, rs, 1);
            l[i] = l[i] * sc + rs;
            m[i] = mnew;
            #pragma unroll
            for (int j = 0; j < 4; ++j) o[i][j] *= sc;
        }
        __syncthreads();

        #pragma unroll 4
        for (int kk = 0; kk < 64; ++kk) {
            float vv4[4], pv[8];
            #pragma unroll
            for (int j = 0; j < 4; ++j) vv4[j] = Vs[kk*FSTR + tx*4+j];
            #pragma unroll
            for (int i = 0; i < 8; ++i) pv[i] = Ps[(ty*8+i)*FSTR + kk];
            #pragma unroll
            for (int i = 0; i < 8; ++i)
                #pragma unroll
                for (int j = 0; j < 4; ++j)
                    o[i][j] = fmaf(pv[i], vv4[j], o[i][j]);
        }
        __syncthreads();
    }

    #pragma unroll
    for (int i = 0; i < 8; ++i) {
        int r = qt * 64 + ty * 8 + i;
        float invl = 1.0f / l[i];
        float a0 = o[i][0]*invl, a1 = o[i][1]*invl, a2 = o[i][2]*invl, a3 = o[i][3]*invl;
        __nv_bfloat16 h0,h1,h2,h3,l0,l1,l2,l3;
        split_bf16(a0,h0,l0); split_bf16(a1,h1,l1); split_bf16(a2,h2,l2); split_bf16(a3,h3,l3);
        size_t off = ((size_t)(b * SS + r)) * DDIM + h * HDIM + tx * 4;
        ((__nv_bfloat162*)(cxh+off))[0] = __halves2bfloat162(h0,h1);
        ((__nv_bfloat162*)(cxh+off))[1] = __halves2bfloat162(h2,h3);
        ((__nv_bfloat162*)(cxl+off))[0] = __halves2bfloat162(l0,l1);
        ((__nv_bfloat162*)(cxl+off))[1] = __halves2bfloat162(l2,l3);
    }
}

// ---------------- launch ----------------
extern "C" void kernel_launch(void* const* d_in, const int* in_sizes, int n_in,
                              void* d_out, int out_size)
{
    const float* x    = (const float*)d_in[0];
    const float* ln1g = (const float*)d_in[2];
    const float* ln1b = (const float*)d_in[3];
    const float* Wq   = (const float*)d_in[4];
    const float* Wk   = (const float*)d_in[5];
    const float* Wv   = (const float*)d_in[6];
    const float* Wo   = (const float*)d_in[7];
    const float* ln2g = (const float*)d_in[8];
    const float* ln2b = (const float*)d_in[9];
    const float* W1   = (const float*)d_in[10];
    const float* W2   = (const float*)d_in[11];

    float* out  = (float*)d_out;
    float* kout = out  + (size_t)MTOK * DDIM;
    float* vout = kout + (size_t)MTOK * DDIM;

    float *qs, *x2;  __nv_bfloat16 *hh, *hl, *cxh, *cxl, *fh, *fl, *wth, *wtl;
    cudaGetSymbolAddress((void**)&qs,  g_q);
    cudaGetSymbolAddress((void**)&x2,  g_x2);
    cudaGetSymbolAddress((void**)&hh,  g_hh);
    cudaGetSymbolAddress((void**)&hl,  g_hl);
    cudaGetSymbolAddress((void**)&cxh, g_cxh);
    cudaGetSymbolAddress((void**)&cxl, g_cxl);
    cudaGetSymbolAddress((void**)&fh,  g_fh);
    cudaGetSymbolAddress((void**)&fl,  g_fl);
    cudaGetSymbolAddress((void**)&wth, g_wth);
    cudaGetSymbolAddress((void**)&wtl, g_wtl);

    const size_t M1 = 1048576;
    __nv_bfloat16 *wqh = wth,        *wkh = wth + M1,   *wvh = wth + 2*M1;
    __nv_bfloat16 *woh = wth + 3*M1, *w1h = wth + 4*M1, *w2h = wth + 8*M1;
    __nv_bfloat16 *wql = wtl,        *wkl = wtl + M1,   *wvl = wtl + 2*M1;
    __nv_bfloat16 *wol = wtl + 3*M1, *w1l = wtl + 4*M1, *w2l = wtl + 8*M1;

    cudaFuncSetAttribute(flash_k, cudaFuncAttributeMaxDynamicSharedMemorySize, FLASH_SMEM);
    cudaFuncSetAttribute(mma_gemm<EPI_NONE>, cudaFuncAttributeMaxDynamicSharedMemorySize, GSMEM);
    cudaFuncSetAttribute(mma_gemm<EPI_BHSD>, cudaFuncAttributeMaxDynamicSharedMemorySize, GSMEM);
    cudaFuncSetAttribute(mma_gemm<EPI_GELU>, cudaFuncAttributeMaxDynamicSharedMemorySize, GSMEM);
    cudaFuncSetAttribute(mma_gemm<EPI_RES>,  cudaFuncAttributeMaxDynamicSharedMemorySize, GSMEM);

    // weight transpose + hi/lo split
    dim3 gT(16, 16);
    wtrans_k<<<gT, 256>>>(Wq, wqh, wql, DDIM, DDIM);
    wtrans_k<<<gT, 256>>>(Wk, wkh, wkl, DDIM, DDIM);
    wtrans_k<<<gT, 256>>>(Wv, wvh, wvl, DDIM, DDIM);
    wtrans_k<<<gT, 256>>>(Wo, woh, wol, DDIM, DDIM);
    wtrans_k<<<dim3(64, 16), 256>>>(W1, w1h, w1l, DDIM, FF);
    wtrans_k<<<dim3(16, 64), 256>>>(W2, w2h, w2l, FF, DDIM);

    dim3 gQKV(DDIM / 128, MTOK / 128);   // (8, 32)
    dim3 gFFN(FF   / 128, MTOK / 128);   // (32, 32)

    ln_k<<<MTOK, 256>>>(x, ln1g, ln1b, hh, hl);
    mma_gemm<EPI_NONE><<<gQKV, 256, GSMEM>>>(hh, hl, wqh, wql, qs,   nullptr, nullptr, nullptr, DDIM, DDIM);
    mma_gemm<EPI_BHSD><<<gQKV, 256, GSMEM>>>(hh, hl, wkh, wkl, kout, nullptr, nullptr, nullptr, DDIM, DDIM);
    mma_gemm<EPI_BHSD><<<gQKV, 256, GSMEM>>>(hh, hl, wvh, wvl, vout, nullptr, nullptr, nullptr, DDIM, DDIM);
    flash_k<<<dim3(SS / 64, BB * HH), 128, FLASH_SMEM>>>(qs, kout, vout, cxh, cxl);
    mma_gemm<EPI_RES><<<gQKV, 256, GSMEM>>>(cxh, cxl, woh, wol, x2, nullptr, nullptr, x, DDIM, DDIM);
    ln_k<<<MTOK, 256>>>(x2, ln2g, ln2b, hh, hl);
    mma_gemm<EPI_GELU><<<gFFN, 256, GSMEM>>>(hh, hl, w1h, w1l, nullptr, fh, fl, nullptr, FF, DDIM);
    mma_gemm<EPI_RES><<<gQKV, 256, GSMEM>>>(fh, fl, w2h, w2l, out, nullptr, nullptr, x2, DDIM, FF);
}

// round 6
// speedup vs baseline: 1.9512x; 1.1516x over previous
#include <cuda_runtime.h>
#include <cuda_bf16.h>
#include <math.h>
#include <stdint.h>

#define BB 2
#define SS 2048
#define DDIM 1024
#define HH 16
#define HDIM 64
#define FF 4096
#define MTOK (BB*SS)

// ---------------- scratch ----------------
__device__ __align__(128) float g_q  [MTOK*DDIM];
__device__ __align__(128) float g_x2 [MTOK*DDIM];
__device__ __align__(128) __nv_bfloat16 g_hh [MTOK*DDIM];
__device__ __align__(128) __nv_bfloat16 g_hl [MTOK*DDIM];
__device__ __align__(128) __nv_bfloat16 g_cxh[MTOK*DDIM];
__device__ __align__(128) __nv_bfloat16 g_cxl[MTOK*DDIM];
__device__ __align__(128) __nv_bfloat16 g_fh [MTOK*FF];
__device__ __align__(128) __nv_bfloat16 g_fl [MTOK*FF];
#define WT_TOTAL 12582912
__device__ __align__(128) __nv_bfloat16 g_wth[WT_TOTAL];
__device__ __align__(128) __nv_bfloat16 g_wtl[WT_TOTAL];

// ---------------- helpers ----------------
__device__ __forceinline__ uint32_t smem_u32(const void* p) {
    uint32_t a;
    asm("{ .reg .u64 t; cvta.to.shared.u64 t, %1; cvt.u32.u64 %0, t; }" : "=r"(a) : "l"(p));
    return a;
}
__device__ __forceinline__ void cp16(uint32_t dst, const void* src) {
    asm volatile("cp.async.cg.shared.global [%0], [%1], 16;" :: "r"(dst), "l"(src) : "memory");
}
#define CP_COMMIT() asm volatile("cp.async.commit_group;" ::: "memory")
#define CP_WAIT(n)  asm volatile("cp.async.wait_group %0;" :: "n"(n) : "memory")

__device__ __forceinline__ void ldsm4(uint32_t* r, uint32_t addr) {
    asm volatile("ldmatrix.sync.aligned.m8n8.x4.shared.b16 {%0,%1,%2,%3}, [%4];"
        : "=r"(r[0]), "=r"(r[1]), "=r"(r[2]), "=r"(r[3]) : "r"(addr));
}
__device__ __forceinline__ void mma16816(float* c, const uint32_t* a, const uint32_t* b) {
    asm volatile("mma.sync.aligned.m16n8k16.row.col.f32.bf16.bf16.f32 "
        "{%0,%1,%2,%3}, {%4,%5,%6,%7}, {%8,%9}, {%0,%1,%2,%3};"
        : "+f"(c[0]), "+f"(c[1]), "+f"(c[2]), "+f"(c[3])
        : "r"(a[0]), "r"(a[1]), "r"(a[2]), "r"(a[3]), "r"(b[0]), "r"(b[1]));
}
typedef unsigned long long ull;
__device__ __forceinline__ ull ffma2(ull a, ull b, ull c) {
    ull d;
    asm("fma.rn.f32x2 %0, %1, %2, %3;" : "=l"(d) : "l"(a), "l"(b), "l"(c));
    return d;
}
__device__ __forceinline__ ull dup2(float x) {
    ull d; unsigned int xi = __float_as_uint(x);
    asm("mov.b64 %0, {%1, %1};" : "=l"(d) : "r"(xi));
    return d;
}
__device__ __forceinline__ ull pack2(float x, float y) {
    ull d;
    asm("mov.b64 %0, {%1, %2};" : "=l"(d) : "r"(__float_as_uint(x)), "r"(__float_as_uint(y)));
    return d;
}
__device__ __forceinline__ float lo2(ull v) { return __uint_as_float((unsigned)(v & 0xffffffffull)); }
__device__ __forceinline__ float hi2(ull v) { return __uint_as_float((unsigned)(v >> 32)); }

__device__ __forceinline__ void split_bf16(float x, __nv_bfloat16& h, __nv_bfloat16& l) {
    h = __float2bfloat16_rn(x);
    l = __float2bfloat16_rn(x - __bfloat162float(h));
}
__device__ __forceinline__ float gelu_exact(float x) {
    return 0.5f * x * (1.0f + erff(x * 0.70710678118654752f));
}

// ---------------- LayerNorm -> bf16 hi/lo ----------------
__global__ __launch_bounds__(256)
void ln_k(const float* __restrict__ x, const float* __restrict__ gg,
          const float* __restrict__ bb,
          __nv_bfloat16* __restrict__ oh, __nv_bfloat16* __restrict__ ol)
{
    __shared__ float red[32];
    int row = blockIdx.x, tid = threadIdx.x;
    float4 v = *(const float4*)(x + (size_t)row * DDIM + tid * 4);
    float s = v.x + v.y + v.z + v.w;
    float s2 = v.x*v.x + v.y*v.y + v.z*v.z + v.w*v.w;
    #pragma unroll
    for (int off = 16; off; off >>= 1) {
        s  += __shfl_xor_sync(0xffffffffu, s,  off);
        s2 += __shfl_xor_sync(0xffffffffu, s2, off);
    }
    int warp = tid >> 5, lane = tid & 31;
    if (lane == 0) { red[warp] = s; red[warp + 8] = s2; }
    __syncthreads();
    if (tid == 0) {
        float ts = 0.f, ts2 = 0.f;
        #pragma unroll
        for (int w = 0; w < 8; ++w) { ts += red[w]; ts2 += red[w + 8]; }
        red[16] = ts; red[17] = ts2;
    }
    __syncthreads();
    float mean = red[16] * (1.0f / DDIM);
    float var  = red[17] * (1.0f / DDIM) - mean * mean;
    float inv  = rsqrtf(var + 1e-5f);
    float4 gv = *(const float4*)(gg + tid * 4);
    float4 bv = *(const float4*)(bb + tid * 4);
    float o0 = (v.x-mean)*inv*gv.x + bv.x, o1 = (v.y-mean)*inv*gv.y + bv.y;
    float o2 = (v.z-mean)*inv*gv.z + bv.z, o3 = (v.w-mean)*inv*gv.w + bv.w;
    __nv_bfloat16 h0,h1,h2,h3,l0,l1,l2,l3;
    split_bf16(o0,h0,l0); split_bf16(o1,h1,l1); split_bf16(o2,h2,l2); split_bf16(o3,h3,l3);
    size_t off = (size_t)row * DDIM + tid * 4;
    ((__nv_bfloat162*)(oh+off))[0] = __halves2bfloat162(h0,h1);
    ((__nv_bfloat162*)(oh+off))[1] = __halves2bfloat162(h2,h3);
    ((__nv_bfloat162*)(ol+off))[0] = __halves2bfloat162(l0,l1);
    ((__nv_bfloat162*)(ol+off))[1] = __halves2bfloat162(l2,l3);
}

// ---------------- weight transpose + split: W[K,N] -> T[N,K] hi/lo ----------------
__global__ __launch_bounds__(256)
void wtrans_k(const float* __restrict__ W, __nv_bfloat16* __restrict__ Th,
              __nv_bfloat16* __restrict__ Tl, int K, int N)
{
    __shared__ __nv_bfloat16 sh[64][65], sl[64][65];
    int n0 = blockIdx.x * 64, k0 = blockIdx.y * 64, tid = threadIdx.x;
    for (int idx = tid; idx < 4096; idx += 256) {
        int i = idx >> 6, j = idx & 63;
        float w = W[(size_t)(k0 + i) * N + n0 + j];
        __nv_bfloat16 h, l; split_bf16(w, h, l);
        sh[i][j] = h; sl[i][j] = l;
    }
    __syncthreads();
    for (int idx = tid; idx < 4096; idx += 256) {
        int n = idx >> 6, k = idx & 63;
        size_t off = (size_t)(n0 + n) * K + k0 + k;
        Th[off] = sh[k][n]; Tl[off] = sl[k][n];
    }
}

// ---------------- mma.sync GEMM 128x128, 4-stage k16 pipeline ----------------
#define EPI_NONE 0
#define EPI_BHSD 1
#define EPI_GELU 2
#define EPI_RES  3
#define PITCH 48                  /* bytes per smem row: 16 bf16 (32B) + 16B pad */
#define ARR_B (128 * PITCH)       /* 6144 */
#define STG_B (4 * ARR_B)         /* 24576 */
#define NSTG 4
#define GSMEM (NSTG * STG_B)      /* 98304 */

template<int EPI>
__global__ __launch_bounds__(256, 2)
void mma_gemm(const __nv_bfloat16* __restrict__ Ah, const __nv_bfloat16* __restrict__ Al,
              const __nv_bfloat16* __restrict__ Bh, const __nv_bfloat16* __restrict__ Bl,
              float* __restrict__ C, __nv_bfloat16* __restrict__ Ch,
              __nv_bfloat16* __restrict__ Cl, const float* __restrict__ R, int N, int K)
{
    extern __shared__ __align__(1024) char smem[];
    const uint32_t sbase = smem_u32(smem);
    const int tid = threadIdx.x, wid = tid >> 5, l = tid & 31;
    const int m0 = blockIdx.y * 128, n0 = blockIdx.x * 128;
    const int wm = wid >> 1, wn = wid & 1;     // warp tile 32x64

    const uint32_t aoff = (uint32_t)((l & 15) * PITCH + (l >> 4) * 16);
    const uint32_t boff = (uint32_t)(((l & 7) + (l >> 4) * 8) * PITCH + ((l >> 3) & 1) * 16);

    float acc[2][8][4];
    #pragma unroll
    for (int i = 0; i < 2; ++i)
        #pragma unroll
        for (int j = 0; j < 8; ++j)
            #pragma unroll
            for (int q = 0; q < 4; ++q) acc[i][j][q] = 0.f;

    const int T = K >> 4;   // k16 stages
    const int r = tid >> 1, cc = tid & 1;

    auto ld_stage = [&](int s) {
        uint32_t dst = sbase + (uint32_t)((s & 3) * STG_B);
        int ko = s * 16;
        uint32_t so = dst + (uint32_t)(r * PITCH + cc * 16);
        size_t ga = (size_t)(m0 + r) * K + ko + cc * 8;
        size_t gb = (size_t)(n0 + r) * K + ko + cc * 8;
        cp16(so,             Ah + ga);
        cp16(so + ARR_B,     Al + ga);
        cp16(so + 2*ARR_B,   Bh + gb);
        cp16(so + 3*ARR_B,   Bl + gb);
    };

    ld_stage(0); CP_COMMIT();
    ld_stage(1); CP_COMMIT();
    ld_stage(2); CP_COMMIT();

    for (int s = 0; s < T; ++s) {
        CP_WAIT(2);
        __syncthreads();
        uint32_t buf = sbase + (uint32_t)((s & 3) * STG_B);
        uint32_t ah[2][4], al[2][4], bh[8][2], bl[8][2];
        #pragma unroll
        for (int i = 0; i < 2; ++i) {
            uint32_t ro = (uint32_t)((wm * 32 + i * 16) * PITCH);
            ldsm4(ah[i], buf + ro + aoff);
            ldsm4(al[i], buf + ARR_B + ro + aoff);
        }
        #pragma unroll
        for (int jp = 0; jp < 4; ++jp) {
            uint32_t ro = (uint32_t)((wn * 64 + jp * 16) * PITCH);
            uint32_t rh[4], rl[4];
            ldsm4(rh, buf + 2*ARR_B + ro + boff);
            ldsm4(rl, buf + 3*ARR_B + ro + boff);
            bh[jp*2+0][0] = rh[0]; bh[jp*2+0][1] = rh[1];
            bh[jp*2+1][0] = rh[2]; bh[jp*2+1][1] = rh[3];
            bl[jp*2+0][0] = rl[0]; bl[jp*2+0][1] = rl[1];
            bl[jp*2+1][0] = rl[2]; bl[jp*2+1][1] = rl[3];
        }
        #pragma unroll
        for (int i = 0; i < 2; ++i)
            #pragma unroll
            for (int j = 0; j < 8; ++j) {
                mma16816(acc[i][j], ah[i], bh[j]);
                mma16816(acc[i][j], ah[i], bl[j]);
                mma16816(acc[i][j], al[i], bh[j]);
            }
        if (s + 3 < T) ld_stage(s + 3);
        CP_COMMIT();
    }

    // ---- epilogue ----
    #pragma unroll
    for (int i = 0; i < 2; ++i)
        #pragma unroll
        for (int j = 0; j < 8; ++j)
            #pragma unroll
            for (int h2 = 0; h2 < 2; ++h2) {
                int rr = m0 + wm * 32 + i * 16 + (l >> 2) + h2 * 8;
                int col = n0 + wn * 64 + j * 8 + (l & 3) * 2;
                float v0 = acc[i][j][h2 * 2 + 0];
                float v1 = acc[i][j][h2 * 2 + 1];
                if (EPI == EPI_GELU) {
                    v0 = gelu_exact(v0); v1 = gelu_exact(v1);
                    __nv_bfloat16 h0, h1, l0, l1;
                    split_bf16(v0, h0, l0); split_bf16(v1, h1, l1);
                    size_t off = (size_t)rr * N + col;
                    *(__nv_bfloat162*)(Ch + off) = __halves2bfloat162(h0, h1);
                    *(__nv_bfloat162*)(Cl + off) = __halves2bfloat162(l0, l1);
                } else if (EPI == EPI_BHSD) {
                    int bb = rr >> 11, sx = rr & 2047;
                    int hidx = col >> 6, hd = col & 63;
                    size_t off = (((size_t)(bb * HH + hidx)) * SS + sx) * HDIM + hd;
                    float2 o; o.x = v0; o.y = v1;
                    *(float2*)(C + off) = o;
                } else if (EPI == EPI_RES) {
                    size_t off = (size_t)rr * N + col;
                    float2 rv = *(const float2*)(R + off);
                    float2 o; o.x = v0 + rv.x; o.y = v1 + rv.y;
                    *(float2*)(C + off) = o;
                } else {
                    size_t off = (size_t)rr * N + col;
                    float2 o; o.x = v0; o.y = v1;
                    *(float2*)(C + off) = o;
                }
            }
}

// ---------------- Flash attention (fp32, transposed Q/K tiles, FFMA2) ----------------
#define FP 68
#define FLASH_SMEM (4 * 64 * FP * 4)   /* 69632 bytes */

__global__ __launch_bounds__(128)
void flash_k(const float* __restrict__ q, const float* __restrict__ kg,
             const float* __restrict__ vg,
             __nv_bfloat16* __restrict__ cxh, __nv_bfloat16* __restrict__ cxl)
{
    extern __shared__ float sm[];
    float* QsT = sm;                 // [d][r] pitch FP
    float* KsT = QsT + 64 * FP;      // [d][r]
    float* Vs  = KsT + 64 * FP;      // [kk][col]
    float* Ps  = Vs  + 64 * FP;      // [row][kk]

    int qt = blockIdx.x, bh = blockIdx.y;
    int b = bh >> 4, h = bh & 15;
    int tid = threadIdx.x, tx = tid & 15, ty = tid >> 4;

    const float* qb = q  + ((size_t)(b * SS + qt * 64)) * DDIM + h * HDIM;
    const float* kb = kg + (size_t)bh * SS * HDIM;
    const float* vb = vg + (size_t)bh * SS * HDIM;

    // load Q transposed + pre-scale
    for (int i = tid; i < 1024; i += 128) {
        int rr = i >> 4, c = (i & 15) * 4;
        float4 v4 = *(const float4*)(qb + (size_t)rr * DDIM + c);
        QsT[(c+0)*FP + rr] = v4.x * 0.125f;
        QsT[(c+1)*FP + rr] = v4.y * 0.125f;
        QsT[(c+2)*FP + rr] = v4.z * 0.125f;
        QsT[(c+3)*FP + rr] = v4.w * 0.125f;
    }

    float m[8], lsum[8];
    ull o2[8][2];
    #pragma unroll
    for (int i = 0; i < 8; ++i) {
        m[i] = -1e30f; lsum[i] = 0.f;
        o2[i][0] = 0ull; o2[i][1] = 0ull;
    }
    __syncthreads();

    for (int kt = 0; kt <= qt; ++kt) {
        const float* kp = kb + (size_t)kt * 4096;
        const float* vp = vb + (size_t)kt * 4096;
        for (int i = tid; i < 1024; i += 128) {
            int rr = i >> 4, c = (i & 15) * 4;
            float4 kv = *(const float4*)(kp + i * 4);
            KsT[(c+0)*FP + rr] = kv.x; KsT[(c+1)*FP + rr] = kv.y;
            KsT[(c+2)*FP + rr] = kv.z; KsT[(c+3)*FP + rr] = kv.w;
            float4 vv = *(const float4*)(vp + i * 4);
            *(float4*)&Vs[rr * FP + c] = vv;
        }
        __syncthreads();

        ull s2[8][2];
        #pragma unroll
        for (int i = 0; i < 8; ++i) { s2[i][0] = 0ull; s2[i][1] = 0ull; }

        #pragma unroll 4
        for (int d = 0; d < 64; ++d) {
            float4 bv = *(const float4*)&KsT[d * FP + tx * 4];
            float4 a0 = *(const float4*)&QsT[d * FP + ty * 8];
            float4 a1 = *(const float4*)&QsT[d * FP + ty * 8 + 4];
            ull b2lo = pack2(bv.x, bv.y), b2hi = pack2(bv.z, bv.w);
            float aa[8] = {a0.x, a0.y, a0.z, a0.w, a1.x, a1.y, a1.z, a1.w};
            #pragma unroll
            for (int i = 0; i < 8; ++i) {
                ull a2 = dup2(aa[i]);
                s2[i][0] = ffma2(a2, b2lo, s2[i][0]);
                s2[i][1] = ffma2(a2, b2hi, s2[i][1]);
            }
        }

        float s[8][4];
        #pragma unroll
        for (int i = 0; i < 8; ++i) {
            s[i][0] = lo2(s2[i][0]); s[i][1] = hi2(s2[i][0]);
            s[i][2] = lo2(s2[i][1]); s[i][3] = hi2(s2[i][1]);
        }
        if (kt == qt) {
            #pragma unroll
            for (int i = 0; i < 8; ++i)
                #pragma unroll
                for (int j = 0; j < 4; ++j)
                    if (tx*4+j > ty*8+i) s[i][j] = -1e30f;
        }
        #pragma unroll
        for (int i = 0; i < 8; ++i) {
            float rm = fmaxf(fmaxf(s[i][0], s[i][1]), fmaxf(s[i][2], s[i][3]));
            rm = fmaxf(rm, __shfl_xor_sync(0xffffffffu, rm, 8));
            rm = fmaxf(rm, __shfl_xor_sync(0xffffffffu, rm, 4));
            rm = fmaxf(rm, __shfl_xor_sync(0xffffffffu, rm, 2));
            rm = fmaxf(rm, __shfl_xor_sync(0xffffffffu, rm, 1));
            float mnew = fmaxf(m[i], rm);
            float sc = __expf(m[i] - mnew);
            float rs = 0.f;
            #pragma unroll
            for (int j = 0; j < 4; ++j) {
                float p = __expf(s[i][j] - mnew);
                s[i][j] = p; rs += p;
                Ps[(ty*8+i)*FP + tx*4+j] = p;
            }
            rs += __shfl_xor_sync(0xffffffffu, rs, 8);
            rs += __shfl_xor_sync(0xffffffffu, rs, 4);
            rs += __shfl_xor_sync(0xffffffffu, rs, 2);
            rs += __shfl_xor_sync(0xffffffffu, rs, 1);
            lsum[i] = lsum[i] * sc + rs;
            m[i] = mnew;
            ull sc2 = dup2(sc);
            o2[i][0] = ffma2(o2[i][0], sc2, 0ull);
            o2[i][1] = ffma2(o2[i][1], sc2, 0ull);
        }
        __syncthreads();

        #pragma unroll 4
        for (int kk = 0; kk < 64; ++kk) {
            float4 vv = *(const float4*)&Vs[kk * FP + tx * 4];
            ull v2lo = pack2(vv.x, vv.y), v2hi = pack2(vv.z, vv.w);
            #pragma unroll
            for (int i = 0; i < 8; ++i) {
                ull p2 = dup2(Ps[(ty*8+i)*FP + kk]);
                o2[i][0] = ffma2(p2, v2lo, o2[i][0]);
                o2[i][1] = ffma2(p2, v2hi, o2[i][1]);
            }
        }
        __syncthreads();
    }

    #pragma unroll
    for (int i = 0; i < 8; ++i) {
        int rr = qt * 64 + ty * 8 + i;
        float invl = 1.0f / lsum[i];
        float a0 = lo2(o2[i][0])*invl, a1 = hi2(o2[i][0])*invl;
        float a2 = lo2(o2[i][1])*invl, a3 = hi2(o2[i][1])*invl;
        __nv_bfloat16 h0,h1,h2,h3,l0,l1,l2,l3;
        split_bf16(a0,h0,l0); split_bf16(a1,h1,l1); split_bf16(a2,h2,l2); split_bf16(a3,h3,l3);
        size_t off = ((size_t)(b * SS + rr)) * DDIM + h * HDIM + tx * 4;
        ((__nv_bfloat162*)(cxh+off))[0] = __halves2bfloat162(h0,h1);
        ((__nv_bfloat162*)(cxh+off))[1] = __halves2bfloat162(h2,h3);
        ((__nv_bfloat162*)(cxl+off))[0] = __halves2bfloat162(l0,l1);
        ((__nv_bfloat162*)(cxl+off))[1] = __halves2bfloat162(l2,l3);
    }
}

// ---------------- launch ----------------
extern "C" void kernel_launch(void* const* d_in, const int* in_sizes, int n_in,
                              void* d_out, int out_size)
{
    const float* x    = (const float*)d_in[0];
    const float* ln1g = (const float*)d_in[2];
    const float* ln1b = (const float*)d_in[3];
    const float* Wq   = (const float*)d_in[4];
    const float* Wk   = (const float*)d_in[5];
    const float* Wv   = (const float*)d_in[6];
    const float* Wo   = (const float*)d_in[7];
    const float* ln2g = (const float*)d_in[8];
    const float* ln2b = (const float*)d_in[9];
    const float* W1   = (const float*)d_in[10];
    const float* W2   = (const float*)d_in[11];

    float* out  = (float*)d_out;
    float* kout = out  + (size_t)MTOK * DDIM;
    float* vout = kout + (size_t)MTOK * DDIM;

    float *qs, *x2;  __nv_bfloat16 *hh, *hl, *cxh, *cxl, *fh, *fl, *wth, *wtl;
    cudaGetSymbolAddress((void**)&qs,  g_q);
    cudaGetSymbolAddress((void**)&x2,  g_x2);
    cudaGetSymbolAddress((void**)&hh,  g_hh);
    cudaGetSymbolAddress((void**)&hl,  g_hl);
    cudaGetSymbolAddress((void**)&cxh, g_cxh);
    cudaGetSymbolAddress((void**)&cxl, g_cxl);
    cudaGetSymbolAddress((void**)&fh,  g_fh);
    cudaGetSymbolAddress((void**)&fl,  g_fl);
    cudaGetSymbolAddress((void**)&wth, g_wth);
    cudaGetSymbolAddress((void**)&wtl, g_wtl);

    const size_t M1 = 1048576;
    __nv_bfloat16 *wqh = wth,        *wkh = wth + M1,   *wvh = wth + 2*M1;
    __nv_bfloat16 *woh = wth + 3*M1, *w1h = wth + 4*M1, *w2h = wth + 8*M1;
    __nv_bfloat16 *wql = wtl,        *wkl = wtl + M1,   *wvl = wtl + 2*M1;
    __nv_bfloat16 *wol = wtl + 3*M1, *w1l = wtl + 4*M1, *w2l = wtl + 8*M1;

    cudaFuncSetAttribute(flash_k, cudaFuncAttributeMaxDynamicSharedMemorySize, FLASH_SMEM);
    cudaFuncSetAttribute(mma_gemm<EPI_NONE>, cudaFuncAttributeMaxDynamicSharedMemorySize, GSMEM);
    cudaFuncSetAttribute(mma_gemm<EPI_BHSD>, cudaFuncAttributeMaxDynamicSharedMemorySize, GSMEM);
    cudaFuncSetAttribute(mma_gemm<EPI_GELU>, cudaFuncAttributeMaxDynamicSharedMemorySize, GSMEM);
    cudaFuncSetAttribute(mma_gemm<EPI_RES>,  cudaFuncAttributeMaxDynamicSharedMemorySize, GSMEM);

    dim3 gQKV(DDIM / 128, MTOK / 128);   // (8, 32)
    dim3 gFFN(FF   / 128, MTOK / 128);   // (32, 32)
    dim3 gT(16, 16);

    // launches 1-5 (so the 6th = gemm Q gets profiled by ncu -s 5 -c 1)
    wtrans_k<<<gT, 256>>>(Wq, wqh, wql, DDIM, DDIM);
    wtrans_k<<<gT, 256>>>(Wk, wkh, wkl, DDIM, DDIM);
    wtrans_k<<<gT, 256>>>(Wv, wvh, wvl, DDIM, DDIM);
    wtrans_k<<<gT, 256>>>(Wo, woh, wol, DDIM, DDIM);
    ln_k<<<MTOK, 256>>>(x, ln1g, ln1b, hh, hl);
    // 6th launch:
    mma_gemm<EPI_NONE><<<gQKV, 256, GSMEM>>>(hh, hl, wqh, wql, qs,   nullptr, nullptr, nullptr, DDIM, DDIM);
    mma_gemm<EPI_BHSD><<<gQKV, 256, GSMEM>>>(hh, hl, wkh, wkl, kout, nullptr, nullptr, nullptr, DDIM, DDIM);
    mma_gemm<EPI_BHSD><<<gQKV, 256, GSMEM>>>(hh, hl, wvh, wvl, vout, nullptr, nullptr, nullptr, DDIM, DDIM);
    flash_k<<<dim3(SS / 64, BB * HH), 128, FLASH_SMEM>>>(qs, kout, vout, cxh, cxl);
    mma_gemm<EPI_RES><<<gQKV, 256, GSMEM>>>(cxh, cxl, woh, wol, x2, nullptr, nullptr, x, DDIM, DDIM);
    wtrans_k<<<dim3(64, 16), 256>>>(W1, w1h, w1l, DDIM, FF);
    wtrans_k<<<dim3(16, 64), 256>>>(W2, w2h, w2l, FF, DDIM);
    ln_k<<<MTOK, 256>>>(x2, ln2g, ln2b, hh, hl);
    mma_gemm<EPI_GELU><<<gFFN, 256, GSMEM>>>(hh, hl, w1h, w1l, nullptr, fh, fl, nullptr, FF, DDIM);
    mma_gemm<EPI_RES><<<gQKV, 256, GSMEM>>>(fh, fl, w2h, w2l, out, nullptr, nullptr, x2, DDIM, FF);
}

// round 7
// speedup vs baseline: 3.1171x; 1.5975x over previous
#include <cuda_runtime.h>
#include <cuda_fp16.h>
#include <math.h>
#include <stdint.h>

#define BB 2
#define SS 2048
#define DDIM 1024
#define HH 16
#define HDIM 64
#define FF 4096
#define MTOK (BB*SS)

// ---------------- scratch ----------------
__device__ __align__(128) float  g_q  [MTOK*DDIM];
__device__ __align__(128) float  g_x2 [MTOK*DDIM];
__device__ __align__(128) __half g_h  [MTOK*DDIM];   // LN out fp16
__device__ __align__(128) __half g_cx [MTOK*DDIM];   // ctx fp16
__device__ __align__(128) __half g_f  [MTOK*FF];     // gelu out fp16
#define WT_TOTAL 12582912
__device__ __align__(128) __half g_wt [WT_TOTAL];    // transposed weights fp16

// ---------------- helpers ----------------
__device__ __forceinline__ uint32_t smem_u32(const void* p) {
    uint32_t a;
    asm("{ .reg .u64 t; cvta.to.shared.u64 t, %1; cvt.u32.u64 %0, t; }" : "=r"(a) : "l"(p));
    return a;
}
__device__ __forceinline__ void cp16(uint32_t dst, const void* src) {
    asm volatile("cp.async.cg.shared.global [%0], [%1], 16;" :: "r"(dst), "l"(src) : "memory");
}
#define CP_COMMIT() asm volatile("cp.async.commit_group;" ::: "memory")
#define CP_WAIT(n)  asm volatile("cp.async.wait_group %0;" :: "n"(n) : "memory")

__device__ __forceinline__ void ldsm4(uint32_t* r, uint32_t addr) {
    asm volatile("ldmatrix.sync.aligned.m8n8.x4.shared.b16 {%0,%1,%2,%3}, [%4];"
        : "=r"(r[0]), "=r"(r[1]), "=r"(r[2]), "=r"(r[3]) : "r"(addr));
}
__device__ __forceinline__ void mma16816(float* c, const uint32_t* a, const uint32_t* b) {
    asm volatile("mma.sync.aligned.m16n8k16.row.col.f32.f16.f16.f32 "
        "{%0,%1,%2,%3}, {%4,%5,%6,%7}, {%8,%9}, {%0,%1,%2,%3};"
        : "+f"(c[0]), "+f"(c[1]), "+f"(c[2]), "+f"(c[3])
        : "r"(a[0]), "r"(a[1]), "r"(a[2]), "r"(a[3]), "r"(b[0]), "r"(b[1]));
}
typedef unsigned long long ull;
__device__ __forceinline__ ull ffma2(ull a, ull b, ull c) {
    ull d;
    asm("fma.rn.f32x2 %0, %1, %2, %3;" : "=l"(d) : "l"(a), "l"(b), "l"(c));
    return d;
}
__device__ __forceinline__ ull dup2(float x) {
    ull d; unsigned int xi = __float_as_uint(x);
    asm("mov.b64 %0, {%1, %1};" : "=l"(d) : "r"(xi));
    return d;
}
__device__ __forceinline__ ull pack2(float x, float y) {
    ull d;
    asm("mov.b64 %0, {%1, %2};" : "=l"(d) : "r"(__float_as_uint(x)), "r"(__float_as_uint(y)));
    return d;
}
__device__ __forceinline__ float lo2(ull v) { return __uint_as_float((unsigned)(v & 0xffffffffull)); }
__device__ __forceinline__ float hi2(ull v) { return __uint_as_float((unsigned)(v >> 32)); }

__device__ __forceinline__ float gelu_exact(float x) {
    return 0.5f * x * (1.0f + erff(x * 0.70710678118654752f));
}

// ---------------- LayerNorm -> fp16 ----------------
__global__ __launch_bounds__(256)
void ln_k(const float* __restrict__ x, const float* __restrict__ gg,
          const float* __restrict__ bb, __half* __restrict__ oh)
{
    __shared__ float red[32];
    int row = blockIdx.x, tid = threadIdx.x;
    float4 v = *(const float4*)(x + (size_t)row * DDIM + tid * 4);
    float s = v.x + v.y + v.z + v.w;
    float s2 = v.x*v.x + v.y*v.y + v.z*v.z + v.w*v.w;
    #pragma unroll
    for (int off = 16; off; off >>= 1) {
        s  += __shfl_xor_sync(0xffffffffu, s,  off);
        s2 += __shfl_xor_sync(0xffffffffu, s2, off);
    }
    int warp = tid >> 5, lane = tid & 31;
    if (lane == 0) { red[warp] = s; red[warp + 8] = s2; }
    __syncthreads();
    if (tid == 0) {
        float ts = 0.f, ts2 = 0.f;
        #pragma unroll
        for (int w = 0; w < 8; ++w) { ts += red[w]; ts2 += red[w + 8]; }
        red[16] = ts; red[17] = ts2;
    }
    __syncthreads();
    float mean = red[16] * (1.0f / DDIM);
    float var  = red[17] * (1.0f / DDIM) - mean * mean;
    float inv  = rsqrtf(var + 1e-5f);
    float4 gv = *(const float4*)(gg + tid * 4);
    float4 bv = *(const float4*)(bb + tid * 4);
    float o0 = (v.x-mean)*inv*gv.x + bv.x, o1 = (v.y-mean)*inv*gv.y + bv.y;
    float o2 = (v.z-mean)*inv*gv.z + bv.z, o3 = (v.w-mean)*inv*gv.w + bv.w;
    size_t off = (size_t)row * DDIM + tid * 4;
    ((__half2*)(oh+off))[0] = __floats2half2_rn(o0, o1);
    ((__half2*)(oh+off))[1] = __floats2half2_rn(o2, o3);
}

// ---------------- weight transpose: W[K,N] fp32 -> T[N,K] fp16 ----------------
__global__ __launch_bounds__(256)
void wtrans_k(const float* __restrict__ W, __half* __restrict__ Th, int K, int N)
{
    __shared__ __half sh[64][65];
    int n0 = blockIdx.x * 64, k0 = blockIdx.y * 64, tid = threadIdx.x;
    for (int idx = tid; idx < 4096; idx += 256) {
        int i = idx >> 6, j = idx & 63;
        sh[i][j] = __float2half_rn(W[(size_t)(k0 + i) * N + n0 + j]);
    }
    __syncthreads();
    for (int idx = tid; idx < 4096; idx += 256) {
        int n = idx >> 6, k = idx & 63;
        Th[(size_t)(n0 + n) * K + k0 + k] = sh[k][n];
    }
}

// ---------------- fp16 mma GEMM 128x128, k32 x 4-stage pipeline ----------------
#define EPI_QKV  0
#define EPI_GELU 2
#define EPI_RES  3
#define PITCH 80                  /* 32 fp16 (64B) + 16B pad */
#define ARR_B (128 * PITCH)       /* 10240 */
#define STG_B (2 * ARR_B)         /* 20480 */
#define GSMEM (4 * STG_B)         /* 81920 */

template<int EPI>
__global__ __launch_bounds__(256, 2)
void mma_gemm(const __half* __restrict__ A, const __half* __restrict__ B,
              float* __restrict__ C, float* __restrict__ Ck, float* __restrict__ Cv,
              __half* __restrict__ Ch, const float* __restrict__ R, int N, int K)
{
    extern __shared__ __align__(1024) char smem[];
    const uint32_t sbase = smem_u32(smem);
    const int tid = threadIdx.x, wid = tid >> 5, l = tid & 31;
    const int m0 = blockIdx.y * 128, n0 = blockIdx.x * 128;
    const int wm = wid >> 1, wn = wid & 1;

    const uint32_t aoff = (uint32_t)((l & 15) * PITCH + (l >> 4) * 16);
    const uint32_t boff = (uint32_t)(((l & 7) + (l >> 4) * 8) * PITCH + ((l >> 3) & 1) * 16);

    float acc[2][8][4];
    #pragma unroll
    for (int i = 0; i < 2; ++i)
        #pragma unroll
        for (int j = 0; j < 8; ++j)
            #pragma unroll
            for (int q = 0; q < 4; ++q) acc[i][j][q] = 0.f;

    const int T = K >> 5;   // k32 stages

    auto ld_stage = [&](int s) {
        uint32_t dst = sbase + (uint32_t)((s & 3) * STG_B);
        int ko = s * 32;
        #pragma unroll
        for (int q = 0; q < 2; ++q) {
            int i = tid + q * 256;
            int rr = i >> 2, c = i & 3;
            uint32_t so = dst + (uint32_t)(rr * PITCH + c * 16);
            cp16(so,         A + (size_t)(m0 + rr) * K + ko + c * 8);
            cp16(so + ARR_B, B + (size_t)(n0 + rr) * K + ko + c * 8);
        }
    };

    ld_stage(0); CP_COMMIT();
    ld_stage(1); CP_COMMIT();
    ld_stage(2); CP_COMMIT();

    for (int s = 0; s < T; ++s) {
        CP_WAIT(2);
        __syncthreads();
        uint32_t buf = sbase + (uint32_t)((s & 3) * STG_B);
        #pragma unroll
        for (int kk = 0; kk < 2; ++kk) {
            uint32_t kb = (uint32_t)(kk * 32);
            uint32_t ah[2][4], bh[8][2];
            #pragma unroll
            for (int i = 0; i < 2; ++i)
                ldsm4(ah[i], buf + (uint32_t)((wm * 32 + i * 16) * PITCH) + aoff + kb);
            #pragma unroll
            for (int jp = 0; jp < 4; ++jp) {
                uint32_t rh[4];
                ldsm4(rh, buf + ARR_B + (uint32_t)((wn * 64 + jp * 16) * PITCH) + boff + kb);
                bh[jp*2+0][0] = rh[0]; bh[jp*2+0][1] = rh[1];
                bh[jp*2+1][0] = rh[2]; bh[jp*2+1][1] = rh[3];
            }
            #pragma unroll
            for (int i = 0; i < 2; ++i)
                #pragma unroll
                for (int j = 0; j < 8; ++j)
                    mma16816(acc[i][j], ah[i], bh[j]);
        }
        if (s + 3 < T) ld_stage(s + 3);
        CP_COMMIT();
    }

    // ---- epilogue ----
    #pragma unroll
    for (int i = 0; i < 2; ++i)
        #pragma unroll
        for (int j = 0; j < 8; ++j)
            #pragma unroll
            for (int h2 = 0; h2 < 2; ++h2) {
                int rr = m0 + wm * 32 + i * 16 + (l >> 2) + h2 * 8;
                int col = n0 + wn * 64 + j * 8 + (l & 3) * 2;
                float v0 = acc[i][j][h2 * 2 + 0];
                float v1 = acc[i][j][h2 * 2 + 1];
                if (EPI == EPI_QKV) {
                    if (col < DDIM) {
                        float2 o; o.x = v0; o.y = v1;
                        *(float2*)(C + (size_t)rr * DDIM + col) = o;
                    } else {
                        int seg = col >> 10;               // 1=K, 2=V
                        int cc = col & 1023;
                        int bb2 = rr >> 11, sx = rr & 2047;
                        int hidx = cc >> 6, hd = cc & 63;
                        size_t off = (((size_t)(bb2 * HH + hidx)) * SS + sx) * HDIM + hd;
                        float2 o; o.x = v0; o.y = v1;
                        *(float2*)((seg == 1 ? Ck : Cv) + off) = o;
                    }
                } else if (EPI == EPI_GELU) {
                    v0 = gelu_exact(v0); v1 = gelu_exact(v1);
                    *(__half2*)(Ch + (size_t)rr * N + col) = __floats2half2_rn(v0, v1);
                } else { // EPI_RES
                    size_t off = (size_t)rr * N + col;
                    float2 rv = *(const float2*)(R + off);
                    float2 o; o.x = v0 + rv.x; o.y = v1 + rv.y;
                    *(float2*)(C + off) = o;
                }
            }
}

// ---------------- Flash attention (fp32, transposed Q/K tiles, FFMA2) ----------------
#define FP 68
#define FLASH_SMEM (4 * 64 * FP * 4)

__global__ __launch_bounds__(128)
void flash_k(const float* __restrict__ q, const float* __restrict__ kg,
             const float* __restrict__ vg, __half* __restrict__ cx)
{
    extern __shared__ float sm[];
    float* QsT = sm;
    float* KsT = QsT + 64 * FP;
    float* Vs  = KsT + 64 * FP;
    float* Ps  = Vs  + 64 * FP;

    int qt = blockIdx.x, bh = blockIdx.y;
    int b = bh >> 4, h = bh & 15;
    int tid = threadIdx.x, tx = tid & 15, ty = tid >> 4;

    const float* qb = q  + ((size_t)(b * SS + qt * 64)) * DDIM + h * HDIM;
    const float* kb = kg + (size_t)bh * SS * HDIM;
    const float* vb = vg + (size_t)bh * SS * HDIM;

    for (int i = tid; i < 1024; i += 128) {
        int rr = i >> 4, c = (i & 15) * 4;
        float4 v4 = *(const float4*)(qb + (size_t)rr * DDIM + c);
        QsT[(c+0)*FP + rr] = v4.x * 0.125f;
        QsT[(c+1)*FP + rr] = v4.y * 0.125f;
        QsT[(c+2)*FP + rr] = v4.z * 0.125f;
        QsT[(c+3)*FP + rr] = v4.w * 0.125f;
    }
    float m[8], lsum[8];
    ull o2[8][2];
    #pragma unroll
    for (int i = 0; i < 8; ++i) {
        m[i] = -1e30f; lsum[i] = 0.f;
        o2[i][0] = 0ull; o2[i][1] = 0ull;
    }
    __syncthreads();

    for (int kt = 0; kt <= qt; ++kt) {
        const float* kp = kb + (size_t)kt * 4096;
        const float* vp = vb + (size_t)kt * 4096;
        for (int i = tid; i < 1024; i += 128) {
            int rr = i >> 4, c = (i & 15) * 4;
            float4 kv = *(const float4*)(kp + i * 4);
            KsT[(c+0)*FP + rr] = kv.x; KsT[(c+1)*FP + rr] = kv.y;
            KsT[(c+2)*FP + rr] = kv.z; KsT[(c+3)*FP + rr] = kv.w;
            float4 vv = *(const float4*)(vp + i * 4);
            *(float4*)&Vs[rr * FP + c] = vv;
        }
        __syncthreads();

        ull s2[8][2];
        #pragma unroll
        for (int i = 0; i < 8; ++i) { s2[i][0] = 0ull; s2[i][1] = 0ull; }

        #pragma unroll 4
        for (int d = 0; d < 64; ++d) {
            float4 bv = *(const float4*)&KsT[d * FP + tx * 4];
            float4 a0 = *(const float4*)&QsT[d * FP + ty * 8];
            float4 a1 = *(const float4*)&QsT[d * FP + ty * 8 + 4];
            ull b2lo = pack2(bv.x, bv.y), b2hi = pack2(bv.z, bv.w);
            float aa[8] = {a0.x, a0.y, a0.z, a0.w, a1.x, a1.y, a1.z, a1.w};
            #pragma unroll
            for (int i = 0; i < 8; ++i) {
                ull a2 = dup2(aa[i]);
                s2[i][0] = ffma2(a2, b2lo, s2[i][0]);
                s2[i][1] = ffma2(a2, b2hi, s2[i][1]);
            }
        }

        float s[8][4];
        #pragma unroll
        for (int i = 0; i < 8; ++i) {
            s[i][0] = lo2(s2[i][0]); s[i][1] = hi2(s2[i][0]);
            s[i][2] = lo2(s2[i][1]); s[i][3] = hi2(s2[i][1]);
        }
        if (kt == qt) {
            #pragma unroll
            for (int i = 0; i < 8; ++i)
                #pragma unroll
                for (int j = 0; j < 4; ++j)
                    if (tx*4+j > ty*8+i) s[i][j] = -1e30f;
        }
        #pragma unroll
        for (int i = 0; i < 8; ++i) {
            float rm = fmaxf(fmaxf(s[i][0], s[i][1]), fmaxf(s[i][2], s[i][3]));
            rm = fmaxf(rm, __shfl_xor_sync(0xffffffffu, rm, 8));
            rm = fmaxf(rm, __shfl_xor_sync(0xffffffffu, rm, 4));
            rm = fmaxf(rm, __shfl_xor_sync(0xffffffffu, rm, 2));
            rm = fmaxf(rm, __shfl_xor_sync(0xffffffffu, rm, 1));
            float mnew = fmaxf(m[i], rm);
            float sc = __expf(m[i] - mnew);
            float rs = 0.f;
            #pragma unroll
            for (int j = 0; j < 4; ++j) {
                float p = __expf(s[i][j] - mnew);
                s[i][j] = p; rs += p;
                Ps[(ty*8+i)*FP + tx*4+j] = p;
            }
            rs += __shfl_xor_sync(0xffffffffu, rs, 8);
            rs += __shfl_xor_sync(0xffffffffu, rs, 4);
            rs += __shfl_xor_sync(0xffffffffu, rs, 2);
            rs += __shfl_xor_sync(0xffffffffu, rs, 1);
            lsum[i] = lsum[i] * sc + rs;
            m[i] = mnew;
            ull sc2 = dup2(sc);
            o2[i][0] = ffma2(o2[i][0], sc2, 0ull);
            o2[i][1] = ffma2(o2[i][1], sc2, 0ull);
        }
        __syncthreads();

        #pragma unroll 4
        for (int kk = 0; kk < 64; ++kk) {
            float4 vv = *(const float4*)&Vs[kk * FP + tx * 4];
            ull v2lo = pack2(vv.x, vv.y), v2hi = pack2(vv.z, vv.w);
            #pragma unroll
            for (int i = 0; i < 8; ++i) {
                ull p2 = dup2(Ps[(ty*8+i)*FP + kk]);
                o2[i][0] = ffma2(p2, v2lo, o2[i][0]);
                o2[i][1] = ffma2(p2, v2hi, o2[i][1]);
            }
        }
        __syncthreads();
    }

    #pragma unroll
    for (int i = 0; i < 8; ++i) {
        int rr = qt * 64 + ty * 8 + i;
        float invl = 1.0f / lsum[i];
        float a0 = lo2(o2[i][0])*invl, a1 = hi2(o2[i][0])*invl;
        float a2 = lo2(o2[i][1])*invl, a3 = hi2(o2[i][1])*invl;
        size_t off = ((size_t)(b * SS + rr)) * DDIM + h * HDIM + tx * 4;
        ((__half2*)(cx+off))[0] = __floats2half2_rn(a0, a1);
        ((__half2*)(cx+off))[1] = __floats2half2_rn(a2, a3);
    }
}

// ---------------- launch ----------------
extern "C" void kernel_launch(void* const* d_in, const int* in_sizes, int n_in,
                              void* d_out, int out_size)
{
    const float* x    = (const float*)d_in[0];
    const float* ln1g = (const float*)d_in[2];
    const float* ln1b = (const float*)d_in[3];
    const float* Wq   = (const float*)d_in[4];
    const float* Wk   = (const float*)d_in[5];
    const float* Wv   = (const float*)d_in[6];
    const float* Wo   = (const float*)d_in[7];
    const float* ln2g = (const float*)d_in[8];
    const float* ln2b = (const float*)d_in[9];
    const float* W1   = (const float*)d_in[10];
    const float* W2   = (const float*)d_in[11];

    float* out  = (float*)d_out;
    float* kout = out  + (size_t)MTOK * DDIM;
    float* vout = kout + (size_t)MTOK * DDIM;

    float *qs, *x2;  __half *hh, *cx, *fx, *wt;
    cudaGetSymbolAddress((void**)&qs, g_q);
    cudaGetSymbolAddress((void**)&x2, g_x2);
    cudaGetSymbolAddress((void**)&hh, g_h);
    cudaGetSymbolAddress((void**)&cx, g_cx);
    cudaGetSymbolAddress((void**)&fx, g_f);
    cudaGetSymbolAddress((void**)&wt, g_wt);

    const size_t M1 = 1048576;
    __half *wqkv = wt;                 // [3072,1024]: Wq rows, then Wk, then Wv
    __half *wo   = wt + 3*M1;
    __half *w1   = wt + 4*M1;          // [4096,1024]
    __half *w2   = wt + 8*M1;          // [1024,4096]

    cudaFuncSetAttribute(flash_k, cudaFuncAttributeMaxDynamicSharedMemorySize, FLASH_SMEM);
    cudaFuncSetAttribute(mma_gemm<EPI_QKV>,  cudaFuncAttributeMaxDynamicSharedMemorySize, GSMEM);
    cudaFuncSetAttribute(mma_gemm<EPI_GELU>, cudaFuncAttributeMaxDynamicSharedMemorySize, GSMEM);
    cudaFuncSetAttribute(mma_gemm<EPI_RES>,  cudaFuncAttributeMaxDynamicSharedMemorySize, GSMEM);

    dim3 gQKV(3 * DDIM / 128, MTOK / 128);  // (24, 32)
    dim3 gD  (DDIM / 128, MTOK / 128);      // (8, 32)
    dim3 gF  (FF   / 128, MTOK / 128);      // (32, 32)
    dim3 gT(16, 16);

    wtrans_k<<<gT, 256>>>(Wq, wqkv,          DDIM, DDIM);
    wtrans_k<<<gT, 256>>>(Wk, wqkv + M1,     DDIM, DDIM);
    wtrans_k<<<gT, 256>>>(Wv, wqkv + 2*M1,   DDIM, DDIM);
    wtrans_k<<<gT, 256>>>(Wo, wo,            DDIM, DDIM);
    ln_k<<<MTOK, 256>>>(x, ln1g, ln1b, hh);
    // 6th launch: fused QKV GEMM (profiling target)
    mma_gemm<EPI_QKV><<<gQKV, 256, GSMEM>>>(hh, wqkv, qs, kout, vout, nullptr, nullptr, 3*DDIM, DDIM);
    flash_k<<<dim3(SS / 64, BB * HH), 128, FLASH_SMEM>>>(qs, kout, vout, cx);
    mma_gemm<EPI_RES><<<gD, 256, GSMEM>>>(cx, wo, x2, nullptr, nullptr, nullptr, x, DDIM, DDIM);
    wtrans_k<<<dim3(64, 16), 256>>>(W1, w1, DDIM, FF);
    wtrans_k<<<dim3(16, 64), 256>>>(W2, w2, FF, DDIM);
    ln_k<<<MTOK, 256>>>(x2, ln2g, ln2b, hh);
    mma_gemm<EPI_GELU><<<gF, 256, GSMEM>>>(hh, w1, nullptr, nullptr, nullptr, fx, nullptr, FF, DDIM);
    mma_gemm<EPI_RES><<<gD, 256, GSMEM>>>(fx, w2, out, nullptr, nullptr, nullptr, x2, DDIM, FF);
}

// round 9
// speedup vs baseline: 5.3426x; 1.7140x over previous
#include <cuda_runtime.h>
#include <cuda_fp16.h>
#include <math.h>
#include <stdint.h>

#define BB 2
#define SS 2048
#define DDIM 1024
#define HH 16
#define HDIM 64
#define FF 4096
#define MTOK (BB*SS)

// ---------------- scratch ----------------
__device__ __align__(128) float  g_x2 [MTOK*DDIM];
__device__ __align__(128) __half g_h  [MTOK*DDIM];
__device__ __align__(128) __half g_cx [MTOK*DDIM];
__device__ __align__(128) __half g_f  [MTOK*FF];
__device__ __align__(128) __half g_qh [MTOK*DDIM];
__device__ __align__(128) __half g_ql [MTOK*DDIM];
__device__ __align__(128) __half g_kh [MTOK*DDIM];
__device__ __align__(128) __half g_kl [MTOK*DDIM];
__device__ __align__(128) __half g_v16[MTOK*DDIM];
#define WT_TOTAL 12582912
__device__ __align__(128) __half g_wt [WT_TOTAL];

// ---------------- helpers ----------------
__device__ __forceinline__ uint32_t smem_u32(const void* p) {
    uint32_t a;
    asm("{ .reg .u64 t; cvta.to.shared.u64 t, %1; cvt.u32.u64 %0, t; }" : "=r"(a) : "l"(p));
    return a;
}
__device__ __forceinline__ uint32_t h2u(__half2 v) {
    uint32_t r;
    memcpy(&r, &v, 4);
    return r;
}
__device__ __forceinline__ void cp16(uint32_t dst, const void* src) {
    asm volatile("cp.async.cg.shared.global [%0], [%1], 16;" :: "r"(dst), "l"(src) : "memory");
}
#define CP_COMMIT() asm volatile("cp.async.commit_group;" ::: "memory")
#define CP_WAIT(n)  asm volatile("cp.async.wait_group %0;" :: "n"(n) : "memory")

__device__ __forceinline__ void ldsm4(uint32_t* r, uint32_t addr) {
    asm volatile("ldmatrix.sync.aligned.m8n8.x4.shared.b16 {%0,%1,%2,%3}, [%4];"
        : "=r"(r[0]), "=r"(r[1]), "=r"(r[2]), "=r"(r[3]) : "r"(addr));
}
__device__ __forceinline__ void ldsm4t(uint32_t* r, uint32_t addr) {
    asm volatile("ldmatrix.sync.aligned.m8n8.x4.trans.shared.b16 {%0,%1,%2,%3}, [%4];"
        : "=r"(r[0]), "=r"(r[1]), "=r"(r[2]), "=r"(r[3]) : "r"(addr));
}
__device__ __forceinline__ void mma16816(float* c, const uint32_t* a, const uint32_t* b) {
    asm volatile("mma.sync.aligned.m16n8k16.row.col.f32.f16.f16.f32 "
        "{%0,%1,%2,%3}, {%4,%5,%6,%7}, {%8,%9}, {%0,%1,%2,%3};"
        : "+f"(c[0]), "+f"(c[1]), "+f"(c[2]), "+f"(c[3])
        : "r"(a[0]), "r"(a[1]), "r"(a[2]), "r"(a[3]), "r"(b[0]), "r"(b[1]));
}
__device__ __forceinline__ float gelu_exact(float x) {
    return 0.5f * x * (1.0f + erff(x * 0.70710678118654752f));
}
// fast exp: 2^n * e^g, no MUFU. rel err ~6e-7. used only for x <= 0.
__device__ __forceinline__ float fexp(float x) {
    float t = fmaxf(x * 1.4426950408889634f, -126.0f);
    float k = t + 12582912.0f;
    int   n = __float_as_int(k) - 0x4B400000;
    float f = t - (k - 12582912.0f);
    float g = f * 0.693147180559945f;
    float p = 1.3888889e-3f;
    p = fmaf(p, g, 8.3333333e-3f);
    p = fmaf(p, g, 4.1666667e-2f);
    p = fmaf(p, g, 1.6666667e-1f);
    p = fmaf(p, g, 5.0e-1f);
    p = fmaf(p, g, 1.0f);
    p = fmaf(p, g, 1.0f);
    return p * __int_as_float((n + 127) << 23);
}

// ---------------- LayerNorm -> fp16 ----------------
__global__ __launch_bounds__(256)
void ln_k(const float* __restrict__ x, const float* __restrict__ gg,
          const float* __restrict__ bb, __half* __restrict__ oh)
{
    __shared__ float red[32];
    int row = blockIdx.x, tid = threadIdx.x;
    float4 v = *(const float4*)(x + (size_t)row * DDIM + tid * 4);
    float s = v.x + v.y + v.z + v.w;
    float s2 = v.x*v.x + v.y*v.y + v.z*v.z + v.w*v.w;
    #pragma unroll
    for (int off = 16; off; off >>= 1) {
        s  += __shfl_xor_sync(0xffffffffu, s,  off);
        s2 += __shfl_xor_sync(0xffffffffu, s2, off);
    }
    int warp = tid >> 5, lane = tid & 31;
    if (lane == 0) { red[warp] = s; red[warp + 8] = s2; }
    __syncthreads();
    if (tid == 0) {
        float ts = 0.f, ts2 = 0.f;
        #pragma unroll
        for (int w = 0; w < 8; ++w) { ts += red[w]; ts2 += red[w + 8]; }
        red[16] = ts; red[17] = ts2;
    }
    __syncthreads();
    float mean = red[16] * (1.0f / DDIM);
    float var  = red[17] * (1.0f / DDIM) - mean * mean;
    float inv  = rsqrtf(var + 1e-5f);
    float4 gv = *(const float4*)(gg + tid * 4);
    float4 bv = *(const float4*)(bb + tid * 4);
    float o0 = (v.x-mean)*inv*gv.x + bv.x, o1 = (v.y-mean)*inv*gv.y + bv.y;
    float o2 = (v.z-mean)*inv*gv.z + bv.z, o3 = (v.w-mean)*inv*gv.w + bv.w;
    size_t off = (size_t)row * DDIM + tid * 4;
    ((__half2*)(oh+off))[0] = __floats2half2_rn(o0, o1);
    ((__half2*)(oh+off))[1] = __floats2half2_rn(o2, o3);
}

// ---------------- merged weight transpose: all 6 matrices in one launch ----------------
__global__ __launch_bounds__(256)
void wtrans_all(const float* __restrict__ Wq, const float* __restrict__ Wk,
                const float* __restrict__ Wv, const float* __restrict__ Wo,
                const float* __restrict__ W1, const float* __restrict__ W2,
                __half* __restrict__ wt)
{
    __shared__ __half sh[64][65];
    int bid = blockIdx.x, tid = threadIdx.x;
    const float* W; __half* T; int K, N, t;
    if (bid < 1024) {
        int seg = bid >> 8; t = bid & 255;
        W = seg == 0 ? Wq : seg == 1 ? Wk : seg == 2 ? Wv : Wo;
        T = wt + (size_t)seg * 1048576; K = 1024; N = 1024;
    } else if (bid < 2048) {
        t = bid - 1024; W = W1; T = wt + (size_t)4 * 1048576; K = 1024; N = 4096;
    } else {
        t = bid - 2048; W = W2; T = wt + (size_t)8 * 1048576; K = 4096; N = 1024;
    }
    int nt = N >> 6;
    int n0 = (t % nt) * 64, k0 = (t / nt) * 64;
    for (int idx = tid; idx < 4096; idx += 256) {
        int i = idx >> 6, j = idx & 63;
        sh[i][j] = __float2half_rn(W[(size_t)(k0 + i) * N + n0 + j]);
    }
    __syncthreads();
    for (int idx = tid; idx < 4096; idx += 256) {
        int n = idx >> 6, k = idx & 63;
        T[(size_t)(n0 + n) * K + k0 + k] = sh[k][n];
    }
}

// ---------------- fp16 mma GEMM 128x128, k32 x 4-stage pipeline ----------------
#define EPI_QKV  0
#define EPI_GELU 2
#define EPI_RES  3
#define PITCH 80
#define ARR_B (128 * PITCH)
#define STG_B (2 * ARR_B)
#define GSMEM (4 * STG_B)

template<int EPI>
__global__ __launch_bounds__(256, 2)
void mma_gemm(const __half* __restrict__ A, const __half* __restrict__ B,
              float* __restrict__ C, float* __restrict__ C2,
              __half* __restrict__ H1, __half* __restrict__ H2,
              __half* __restrict__ H3, __half* __restrict__ H4, __half* __restrict__ H5,
              const float* __restrict__ R, int N, int K)
{
    extern __shared__ __align__(1024) char smem[];
    const uint32_t sbase = smem_u32(smem);
    const int tid = threadIdx.x, wid = tid >> 5, l = tid & 31;
    const int m0 = blockIdx.y * 128, n0 = blockIdx.x * 128;
    const int wm = wid >> 1, wn = wid & 1;

    const uint32_t aoff = (uint32_t)((l & 15) * PITCH + (l >> 4) * 16);
    const uint32_t boff = (uint32_t)(((l & 7) + (l >> 4) * 8) * PITCH + ((l >> 3) & 1) * 16);

    float acc[2][8][4];
    #pragma unroll
    for (int i = 0; i < 2; ++i)
        #pragma unroll
        for (int j = 0; j < 8; ++j)
            #pragma unroll
            for (int q = 0; q < 4; ++q) acc[i][j][q] = 0.f;

    const int T = K >> 5;

    auto ld_stage = [&](int s) {
        uint32_t dst = sbase + (uint32_t)((s & 3) * STG_B);
        int ko = s * 32;
        #pragma unroll
        for (int q = 0; q < 2; ++q) {
            int i = tid + q * 256;
            int rr = i >> 2, c = i & 3;
            uint32_t so = dst + (uint32_t)(rr * PITCH + c * 16);
            cp16(so,         A + (size_t)(m0 + rr) * K + ko + c * 8);
            cp16(so + ARR_B, B + (size_t)(n0 + rr) * K + ko + c * 8);
        }
    };

    ld_stage(0); CP_COMMIT();
    ld_stage(1); CP_COMMIT();
    ld_stage(2); CP_COMMIT();

    for (int s = 0; s < T; ++s) {
        CP_WAIT(2);
        __syncthreads();
        uint32_t buf = sbase + (uint32_t)((s & 3) * STG_B);
        #pragma unroll
        for (int kk = 0; kk < 2; ++kk) {
            uint32_t kb = (uint32_t)(kk * 32);
            uint32_t ah[2][4], bh[8][2];
            #pragma unroll
            for (int i = 0; i < 2; ++i)
                ldsm4(ah[i], buf + (uint32_t)((wm * 32 + i * 16) * PITCH) + aoff + kb);
            #pragma unroll
            for (int jp = 0; jp < 4; ++jp) {
                uint32_t rh[4];
                ldsm4(rh, buf + ARR_B + (uint32_t)((wn * 64 + jp * 16) * PITCH) + boff + kb);
                bh[jp*2+0][0] = rh[0]; bh[jp*2+0][1] = rh[1];
                bh[jp*2+1][0] = rh[2]; bh[jp*2+1][1] = rh[3];
            }
            #pragma unroll
            for (int i = 0; i < 2; ++i)
                #pragma unroll
                for (int j = 0; j < 8; ++j)
                    mma16816(acc[i][j], ah[i], bh[j]);
        }
        if (s + 3 < T) ld_stage(s + 3);
        CP_COMMIT();
    }

    #pragma unroll
    for (int i = 0; i < 2; ++i)
        #pragma unroll
        for (int j = 0; j < 8; ++j)
            #pragma unroll
            for (int h2 = 0; h2 < 2; ++h2) {
                int rr = m0 + wm * 32 + i * 16 + (l >> 2) + h2 * 8;
                int col = n0 + wn * 64 + j * 8 + (l & 3) * 2;
                float v0 = acc[i][j][h2 * 2 + 0];
                float v1 = acc[i][j][h2 * 2 + 1];
                if (EPI == EPI_QKV) {
                    int seg = col >> 10, cc = col & 1023;
                    int bb2 = rr >> 11, sx = rr & 2047;
                    int hidx = cc >> 6, hd = cc & 63;
                    size_t off = (((size_t)(bb2 * HH + hidx)) * SS + sx) * HDIM + hd;
                    if (seg == 0) {
                        float q0v = v0 * 0.125f, q1v = v1 * 0.125f;
                        __half h0 = __float2half_rn(q0v), h1 = __float2half_rn(q1v);
                        *(__half2*)(H1 + off) = __halves2half2(h0, h1);
                        *(__half2*)(H2 + off) = __halves2half2(
                            __float2half_rn(q0v - __half2float(h0)),
                            __float2half_rn(q1v - __half2float(h1)));
                    } else if (seg == 1) {
                        float2 o; o.x = v0; o.y = v1;
                        *(float2*)(C + off) = o;
                        __half h0 = __float2half_rn(v0), h1 = __float2half_rn(v1);
                        *(__half2*)(H3 + off) = __halves2half2(h0, h1);
                        *(__half2*)(H4 + off) = __halves2half2(
                            __float2half_rn(v0 - __half2float(h0)),
                            __float2half_rn(v1 - __half2float(h1)));
                    } else {
                        float2 o; o.x = v0; o.y = v1;
                        *(float2*)(C2 + off) = o;
                        *(__half2*)(H5 + off) = __floats2half2_rn(v0, v1);
                    }
                } else if (EPI == EPI_GELU) {
                    v0 = gelu_exact(v0); v1 = gelu_exact(v1);
                    *(__half2*)(H1 + (size_t)rr * N + col) = __floats2half2_rn(v0, v1);
                } else {
                    size_t off = (size_t)rr * N + col;
                    float2 rv = *(const float2*)(R + off);
                    float2 o; o.x = v0 + rv.x; o.y = v1 + rv.y;
                    *(float2*)(C + off) = o;
                }
            }
}

// ---------------- tensor-core flash attention ----------------
#define QP 144
#define FQ_B (128 * QP)
#define FKV_B (64 * QP)
#define FSTG_B (3 * FKV_B)
#define FSMEM (2 * FQ_B + 2 * FSTG_B)

__global__ __launch_bounds__(256)
void flash_tc(const __half* __restrict__ qh, const __half* __restrict__ ql,
              const __half* __restrict__ kh, const __half* __restrict__ kl,
              const __half* __restrict__ vv, __half* __restrict__ cx)
{
    extern __shared__ __align__(1024) char smem[];
    const uint32_t sb = smem_u32(smem);
    const int qt = blockIdx.x, bh = blockIdx.y;
    const int b = bh >> 4, h = bh & 15;
    const int q0 = qt * 128;
    const int tid = threadIdx.x, wid = tid >> 5, l = tid & 31;

    const __half* qhb = qh + ((size_t)bh * SS + q0) * HDIM;
    const __half* qlb = ql + ((size_t)bh * SS + q0) * HDIM;

    #pragma unroll
    for (int i = 0; i < 4; ++i) {
        int idx = tid + i * 256;
        int r = idx >> 3, c = idx & 7;
        cp16(sb + (uint32_t)(r * QP + c * 16),        qhb + r * 64 + c * 8);
        cp16(sb + FQ_B + (uint32_t)(r * QP + c * 16), qlb + r * 64 + c * 8);
    }
    CP_COMMIT();

    const int nkt = qt * 2 + 2;
    auto ld_kv = [&](int kt2) {
        uint32_t dstb = sb + 2 * FQ_B + (uint32_t)((kt2 & 1) * FSTG_B);
        const __half* kbh = kh + ((size_t)bh * SS + kt2 * 64) * HDIM;
        const __half* kbl = kl + ((size_t)bh * SS + kt2 * 64) * HDIM;
        const __half* vb  = vv + ((size_t)bh * SS + kt2 * 64) * HDIM;
        #pragma unroll
        for (int i = 0; i < 2; ++i) {
            int idx = tid + i * 256;
            int r = idx >> 3, c = idx & 7;
            uint32_t so = (uint32_t)(r * QP + c * 16);
            cp16(dstb + so,            kbh + r * 64 + c * 8);
            cp16(dstb + FKV_B + so,    kbl + r * 64 + c * 8);
            cp16(dstb + 2*FKV_B + so,  vb  + r * 64 + c * 8);
        }
    };
    ld_kv(0); CP_COMMIT();

    const uint32_t aoff = (uint32_t)((l & 15) * QP + (l >> 4) * 16);
    const uint32_t boff = (uint32_t)(((l & 7) + (l >> 4) * 8) * QP + ((l >> 3) & 1) * 16);
    const uint32_t voff = (uint32_t)(((l & 7) + ((l >> 3) & 1) * 8) * QP + (l >> 4) * 16);

    float m2[2] = {-1e30f, -1e30f}, l2[2] = {0.f, 0.f};
    float O[8][4];
    #pragma unroll
    for (int j = 0; j < 8; ++j)
        #pragma unroll
        for (int q = 0; q < 4; ++q) O[j][q] = 0.f;

    for (int kt = 0; kt < nkt; ++kt) {
        if (kt + 1 < nkt) { ld_kv(kt + 1); CP_COMMIT(); CP_WAIT(1); }
        else             { CP_WAIT(0); }
        __syncthreads();

        uint32_t kb = sb + 2 * FQ_B + (uint32_t)((kt & 1) * FSTG_B);
        float S[8][4];
        #pragma unroll
        for (int j = 0; j < 8; ++j)
            #pragma unroll
            for (int q = 0; q < 4; ++q) S[j][q] = 0.f;

        #pragma unroll
        for (int ks = 0; ks < 4; ++ks) {
            uint32_t kadd = (uint32_t)(ks * 32);
            uint32_t aH[4], aL[4];
            ldsm4(aH, sb + (uint32_t)(wid * 16 * QP) + aoff + kadd);
            ldsm4(aL, sb + FQ_B + (uint32_t)(wid * 16 * QP) + aoff + kadd);
            #pragma unroll
            for (int jp = 0; jp < 4; ++jp) {
                uint32_t rH[4], rL[4];
                ldsm4(rH, kb + (uint32_t)(jp * 16 * QP) + boff + kadd);
                ldsm4(rL, kb + FKV_B + (uint32_t)(jp * 16 * QP) + boff + kadd);
                uint32_t bH0[2] = {rH[0], rH[1]}, bH1[2] = {rH[2], rH[3]};
                uint32_t bL0[2] = {rL[0], rL[1]}, bL1[2] = {rL[2], rL[3]};
                mma16816(S[jp*2+0], aH, bH0);
                mma16816(S[jp*2+0], aH, bL0);
                mma16816(S[jp*2+0], aL, bH0);
                mma16816(S[jp*2+1], aH, bH1);
                mma16816(S[jp*2+1], aH, bL1);
                mma16816(S[jp*2+1], aL, bH1);
            }
        }

        if (kt * 64 + 63 > q0 + wid * 16) {
            int rowb = q0 + wid * 16 + (l >> 2);
            int colb = kt * 64 + 2 * (l & 3);
            #pragma unroll
            for (int j = 0; j < 8; ++j)
                #pragma unroll
                for (int q = 0; q < 4; ++q) {
                    int row = rowb + (q >> 1) * 8;
                    int col = colb + 8 * j + (q & 1);
                    if (col > row) S[j][q] = -3.0e38f;
                }
        }

        #pragma unroll
        for (int h2 = 0; h2 < 2; ++h2) {
            float rm = -3.4e38f;
            #pragma unroll
            for (int j = 0; j < 8; ++j)
                rm = fmaxf(rm, fmaxf(S[j][h2*2], S[j][h2*2+1]));
            rm = fmaxf(rm, __shfl_xor_sync(0xffffffffu, rm, 1));
            rm = fmaxf(rm, __shfl_xor_sync(0xffffffffu, rm, 2));
            float mn = fmaxf(m2[h2], rm);
            float sc = fexp(m2[h2] - mn);
            float rs = 0.f;
            #pragma unroll
            for (int j = 0; j < 8; ++j) {
                float p0 = fexp(S[j][h2*2]   - mn);
                float p1 = fexp(S[j][h2*2+1] - mn);
                S[j][h2*2] = p0; S[j][h2*2+1] = p1;
                rs += p0 + p1;
            }
            rs += __shfl_xor_sync(0xffffffffu, rs, 1);
            rs += __shfl_xor_sync(0xffffffffu, rs, 2);
            l2[h2] = l2[h2] * sc + rs;
            m2[h2] = mn;
            #pragma unroll
            for (int j = 0; j < 8; ++j) {
                O[j][h2*2] *= sc; O[j][h2*2+1] *= sc;
            }
        }

        #pragma unroll
        for (int t = 0; t < 4; ++t) {
            uint32_t aP[4];
            aP[0] = h2u(__floats2half2_rn(S[2*t][0],   S[2*t][1]));
            aP[1] = h2u(__floats2half2_rn(S[2*t][2],   S[2*t][3]));
            aP[2] = h2u(__floats2half2_rn(S[2*t+1][0], S[2*t+1][1]));
            aP[3] = h2u(__floats2half2_rn(S[2*t+1][2], S[2*t+1][3]));
            #pragma unroll
            for (int jp = 0; jp < 4; ++jp) {
                uint32_t rV[4];
                ldsm4t(rV, kb + 2*FKV_B + (uint32_t)(t * 16 * QP) + voff + (uint32_t)(jp * 32));
                uint32_t b0[2] = {rV[0], rV[1]}, b1[2] = {rV[2], rV[3]};
                mma16816(O[jp*2+0], aP, b0);
                mma16816(O[jp*2+1], aP, b1);
            }
        }
        __syncthreads();
    }

    #pragma unroll
    for (int h2 = 0; h2 < 2; ++h2) {
        float inv = 1.0f / l2[h2];
        int row = q0 + wid * 16 + (l >> 2) + h2 * 8;
        size_t base = ((size_t)b * SS + row) * DDIM + h * HDIM + 2 * (l & 3);
        #pragma unroll
        for (int j = 0; j < 8; ++j)
            *(__half2*)(cx + base + 8 * j) =
                __floats2half2_rn(O[j][h2*2] * inv, O[j][h2*2+1] * inv);
    }
}

// ---------------- launch ----------------
extern "C" void kernel_launch(void* const* d_in, const int* in_sizes, int n_in,
                              void* d_out, int out_size)
{
    const float* x    = (const float*)d_in[0];
    const float* ln1g = (const float*)d_in[2];
    const float* ln1b = (const float*)d_in[3];
    const float* Wq   = (const float*)d_in[4];
    const float* Wk   = (const float*)d_in[5];
    const float* Wv   = (const float*)d_in[6];
    const float* Wo   = (const float*)d_in[7];
    const float* ln2g = (const float*)d_in[8];
    const float* ln2b = (const float*)d_in[9];
    const float* W1   = (const float*)d_in[10];
    const float* W2   = (const float*)d_in[11];

    float* out  = (float*)d_out;
    float* kout = out  + (size_t)MTOK * DDIM;
    float* vout = kout + (size_t)MTOK * DDIM;

    float *x2; __half *hh, *cx, *fx, *wt, *qh, *ql, *kh, *kl, *v16;
    cudaGetSymbolAddress((void**)&x2,  g_x2);
    cudaGetSymbolAddress((void**)&hh,  g_h);
    cudaGetSymbolAddress((void**)&cx,  g_cx);
    cudaGetSymbolAddress((void**)&fx,  g_f);
    cudaGetSymbolAddress((void**)&wt,  g_wt);
    cudaGetSymbolAddress((void**)&qh,  g_qh);
    cudaGetSymbolAddress((void**)&ql,  g_ql);
    cudaGetSymbolAddress((void**)&kh,  g_kh);
    cudaGetSymbolAddress((void**)&kl,  g_kl);
    cudaGetSymbolAddress((void**)&v16, g_v16);

    const size_t M1 = 1048576;
    __half *wqkv = wt, *wo = wt + 3*M1, *w1 = wt + 4*M1, *w2 = wt + 8*M1;

    cudaFuncSetAttribute(flash_tc, cudaFuncAttributeMaxDynamicSharedMemorySize, FSMEM);
    cudaFuncSetAttribute(mma_gemm<EPI_QKV>,  cudaFuncAttributeMaxDynamicSharedMemorySize, GSMEM);
    cudaFuncSetAttribute(mma_gemm<EPI_GELU>, cudaFuncAttributeMaxDynamicSharedMemorySize, GSMEM);
    cudaFuncSetAttribute(mma_gemm<EPI_RES>,  cudaFuncAttributeMaxDynamicSharedMemorySize, GSMEM);

    dim3 gQKV(3 * DDIM / 128, MTOK / 128);
    dim3 gD  (DDIM / 128, MTOK / 128);
    dim3 gF  (FF   / 128, MTOK / 128);

    wtrans_all<<<3072, 256>>>(Wq, Wk, Wv, Wo, W1, W2, wt);
    ln_k<<<MTOK, 256>>>(x, ln1g, ln1b, hh);
    mma_gemm<EPI_QKV><<<gQKV, 256, GSMEM>>>(hh, wqkv, kout, vout, qh, ql, kh, kl, v16, nullptr, 3*DDIM, DDIM);
    flash_tc<<<dim3(SS / 128, BB * HH), 256, FSMEM>>>(qh, ql, kh, kl, v16, cx);
    mma_gemm<EPI_RES><<<gD, 256, GSMEM>>>(cx, wo, x2, nullptr, nullptr, nullptr, nullptr, nullptr, nullptr, x, DDIM, DDIM);
    ln_k<<<MTOK, 256>>>(x2, ln2g, ln2b, hh);
    mma_gemm<EPI_GELU><<<gF, 256, GSMEM>>>(hh, w1, nullptr, nullptr, fx, nullptr, nullptr, nullptr, nullptr, nullptr, FF, DDIM);
    mma_gemm<EPI_RES><<<gD, 256, GSMEM>>>(fx, w2, out, nullptr, nullptr, nullptr, nullptr, nullptr, nullptr, x2, DDIM, FF);
}